// round 11
// baseline (speedup 1.0000x reference)
#include <cuda_runtime.h>
#include <cuda_bf16.h>
#include <cuda_fp16.h>
#include <math.h>

#define N_TOTAL 102400
#define E_TOTAL 4096000
#define F 256
#define NODES_PER_G 400
#define NUM_G 256
#define NCHUNKS 4
#define NODES_PER_CHUNK (N_TOTAL / NCHUNKS)    // 25600 (= 64 graphs)
#define GRAPHS_PER_CHUNK (NUM_G / NCHUNKS)     // 64

// ---------------- scratch (device globals; no allocation allowed) -----------
__device__ int   g_deg[N_TOTAL];
__device__ int   g_cursor[N_TOTAL];
__device__ int   g_rowptr[N_TOTAL + 1];
__device__ int   g_boff[401];
__device__ int   g_col[E_TOTAL];
__device__ float g_dis[N_TOTAL];
__device__ __half g_hps[(size_t)N_TOTAL * F];   // layer1: gemm1 out / agg1 in
__device__ __half g_p16[(size_t)N_TOTAL * F];   // agg1 out / gemm2 in
__device__ __half g_hps2[(size_t)N_TOTAL * F];  // gemm2 out / agg2 in (no alias!)
__device__ float  g_buf[(size_t)N_TOTAL * F];   // agg2 out (fp32) / readout in
__device__ int   g_is64;
// W1 pre-split bf16 hi/lo, transposed [256][400]; W2 fp16 hi/lo [256][256]
__device__ unsigned short g_w1hi[256 * 400];
__device__ unsigned short g_w1lo[256 * 400];
__device__ unsigned short g_w2hi[256 * 256];
__device__ unsigned short g_w2lo[256 * 256];

__device__ __forceinline__ void cp_async16(void* smem_dst, const void* gmem_src) {
    unsigned long long sa = __cvta_generic_to_shared(smem_dst);
    asm volatile("cp.async.cg.shared.global [%0], [%1], 16;"
                 :: "l"(sa), "l"(gmem_src) : "memory");
}

// ---------------- setup kernels --------------------------------------------
__global__ void detect_kernel(const unsigned int* __restrict__ w) {
    __shared__ int any;
    if (threadIdx.x == 0) any = 0;
    __syncthreads();
    int idx = 1 + 2 * (int)threadIdx.x;
    if (w[idx] != 0u) atomicOr(&any, 1);
    __syncthreads();
    if (threadIdx.x == 0) g_is64 = (any ? 0 : 1);
}

__global__ void count_kernel(const void* __restrict__ ei) {
    int t = blockIdx.x * blockDim.x + threadIdx.x;
    if (t * 2 >= E_TOTAL) return;
    if (g_is64) {
        longlong2 d = ((const longlong2*)((const long long*)ei + E_TOTAL))[t];
        atomicAdd(&g_deg[(int)d.x], 1);
        atomicAdd(&g_deg[(int)d.y], 1);
    } else {
        int2 d = ((const int2*)((const int*)ei + E_TOTAL))[t];
        atomicAdd(&g_deg[d.x], 1);
        atomicAdd(&g_deg[d.y], 1);
    }
}

__global__ void scan1_kernel() {
    __shared__ int s[256];
    int b = blockIdx.x, tid = threadIdx.x;
    int i = b * 256 + tid;
    int d = g_deg[i];
    g_dis[i] = rsqrtf((float)(d + 1));
    s[tid] = d;
    __syncthreads();
#pragma unroll
    for (int off = 1; off < 256; off <<= 1) {
        int t = 0;
        if (tid >= off) t = s[tid - off];
        __syncthreads();
        s[tid] += t;
        __syncthreads();
    }
    g_rowptr[i] = s[tid] - d;
    if (tid == 255) g_boff[b] = s[255];
}

__global__ void scan2_kernel() {
    __shared__ int s[512];
    int tid = threadIdx.x;
    int v = (tid < 400) ? g_boff[tid] : 0;
    s[tid] = v;
    __syncthreads();
#pragma unroll
    for (int off = 1; off < 512; off <<= 1) {
        int t = 0;
        if (tid >= off) t = s[tid - off];
        __syncthreads();
        s[tid] += t;
        __syncthreads();
    }
    if (tid <= 400) g_boff[tid] = s[tid] - v;
}

__global__ void scan3_kernel() {
    int b = blockIdx.x, tid = threadIdx.x;
    int i = b * 256 + tid;
    g_rowptr[i] += g_boff[b];
    if (i == N_TOTAL - 1) g_rowptr[N_TOTAL] = g_boff[400];
}

__global__ void fill_kernel(const void* __restrict__ ei) {
    int t = blockIdx.x * blockDim.x + threadIdx.x;
    if (t * 2 >= E_TOTAL) return;
    int s0, s1, d0, d1;
    if (g_is64) {
        longlong2 s = ((const longlong2*)ei)[t];
        longlong2 d = ((const longlong2*)((const long long*)ei + E_TOTAL))[t];
        s0 = (int)s.x; s1 = (int)s.y; d0 = (int)d.x; d1 = (int)d.y;
    } else {
        int2 s = ((const int2*)ei)[t];
        int2 d = ((const int2*)((const int*)ei + E_TOTAL))[t];
        s0 = s.x; s1 = s.y; d0 = d.x; d1 = d.y;
    }
    int p0 = atomicAdd(&g_cursor[d0], 1);
    g_col[g_rowptr[d0] + p0] = s0;
    int p1 = atomicAdd(&g_cursor[d1], 1);
    g_col[g_rowptr[d1] + p1] = s1;
}

// ---------------- weight split+transpose kernels ----------------------------
__global__ void wsplit_bf16_kernel(const float* __restrict__ W, int K,
                                   unsigned short* __restrict__ hi,
                                   unsigned short* __restrict__ lo) {
    int idx = blockIdx.x * blockDim.x + threadIdx.x;
    if (idx >= K * 256) return;
    int n = idx / K, k = idx % K;
    float a = W[(size_t)k * 256 + n];
    __nv_bfloat16 h = __float2bfloat16_rn(a);
    float hf = __bfloat162float(h);
    __nv_bfloat16 l = __float2bfloat16_rn(a - hf);
    hi[(size_t)n * K + k] = __bfloat16_as_ushort(h);
    lo[(size_t)n * K + k] = __bfloat16_as_ushort(l);
}

__global__ void wsplit_f16_kernel(const float* __restrict__ W, int K,
                                  unsigned short* __restrict__ hi,
                                  unsigned short* __restrict__ lo) {
    int idx = blockIdx.x * blockDim.x + threadIdx.x;
    if (idx >= K * 256) return;
    int n = idx / K, k = idx % K;
    float a = W[(size_t)k * 256 + n];
    __half h = __float2half_rn(a);
    __half l = __float2half_rn(a - __half2float(h));
    hi[(size_t)n * K + k] = __half_as_ushort(h);
    lo[(size_t)n * K + k] = __half_as_ushort(l);
}

// ---------------- shared GEMM machinery -------------------------------------
#define GBK 16
#define SM_STRIDE 48
#define BUF_BYTES 24576
#define OFF_ALO 6144
#define OFF_BHI 12288
#define OFF_BLO 18432
#define BUF2_BYTES 18432
#define OFF2_BHI 6144
#define OFF2_BLO 12288

__device__ __forceinline__ void bsplit2(float a0, float a1,
                                        unsigned int& hi, unsigned int& lo) {
    __nv_bfloat16 h0 = __float2bfloat16_rn(a0);
    __nv_bfloat16 h1 = __float2bfloat16_rn(a1);
    float f0 = __bfloat162float(h0), f1 = __bfloat162float(h1);
    __nv_bfloat16 l0 = __float2bfloat16_rn(a0 - f0);
    __nv_bfloat16 l1 = __float2bfloat16_rn(a1 - f1);
    hi = (unsigned int)__bfloat16_as_ushort(h0) |
         ((unsigned int)__bfloat16_as_ushort(h1) << 16);
    lo = (unsigned int)__bfloat16_as_ushort(l0) |
         ((unsigned int)__bfloat16_as_ushort(l1) << 16);
}

__device__ __forceinline__ void ldsm_x4(unsigned int addr, unsigned int* r) {
    asm volatile("ldmatrix.sync.aligned.m8n8.x4.shared.b16 {%0,%1,%2,%3}, [%4];"
                 : "=r"(r[0]), "=r"(r[1]), "=r"(r[2]), "=r"(r[3]) : "r"(addr));
}
__device__ __forceinline__ void ldsm_x2(unsigned int addr, unsigned int* r) {
    asm volatile("ldmatrix.sync.aligned.m8n8.x2.shared.b16 {%0,%1}, [%2];"
                 : "=r"(r[0]), "=r"(r[1]) : "r"(addr));
}
__device__ __forceinline__ void mma_bf16(float* c, const unsigned int* a,
                                         const unsigned int* b) {
    asm volatile(
        "mma.sync.aligned.m16n8k16.row.col.f32.bf16.bf16.f32 "
        "{%0,%1,%2,%3}, {%4,%5,%6,%7}, {%8,%9}, {%0,%1,%2,%3};"
        : "+f"(c[0]), "+f"(c[1]), "+f"(c[2]), "+f"(c[3])
        : "r"(a[0]), "r"(a[1]), "r"(a[2]), "r"(a[3]), "r"(b[0]), "r"(b[1]));
}
__device__ __forceinline__ void mma_f16(float* c, const unsigned int* a,
                                        const unsigned int* b) {
    asm volatile(
        "mma.sync.aligned.m16n8k16.row.col.f32.f16.f16.f32 "
        "{%0,%1,%2,%3}, {%4,%5,%6,%7}, {%8,%9}, {%0,%1,%2,%3};"
        : "+f"(c[0]), "+f"(c[1]), "+f"(c[2]), "+f"(c[3])
        : "r"(a[0]), "r"(a[1]), "r"(a[2]), "r"(a[3]), "r"(b[0]), "r"(b[1]));
}

// ---- GEMM1: A fp32, W bf16 hi/lo, 3 passes; out = fp16(A@W)  (NO dis) ------
__global__ __launch_bounds__(256) void gemm1_kernel(
    const float* __restrict__ A,
    const unsigned short* __restrict__ Whi,
    const unsigned short* __restrict__ Wlo,
    __half* __restrict__ out, int K)
{
    __shared__ __align__(16) unsigned char smem[2 * BUF_BYTES];
    unsigned int sbase = (unsigned int)__cvta_generic_to_shared(smem);
    int tid = threadIdx.x, lane = tid & 31, wid = tid >> 5;
    int wm = wid & 1, wn = wid >> 1;
    int m0 = blockIdx.y * 128, n0 = blockIdx.x * 128;

    float acc[4][4][4];
#pragma unroll
    for (int i = 0; i < 4; i++)
#pragma unroll
        for (int j = 0; j < 4; j++)
#pragma unroll
            for (int q = 0; q < 4; q++) acc[i][j][q] = 0.f;

    int am[2], akq[2];
    am[0] = tid >> 2;           akq[0] = tid & 3;
    am[1] = (tid + 256) >> 2;   akq[1] = (tid + 256) & 3;
    int bn = tid >> 1, bc = tid & 1;

    const int niter = K / GBK;
    float4 stA[2];

#pragma unroll
    for (int t = 0; t < 2; t++)
        stA[t] = *(const float4*)&A[(size_t)(m0 + am[t]) * K + akq[t] * 4];
    cp_async16(smem + OFF_BHI + bn * SM_STRIDE + bc * 16, &Whi[(size_t)(n0 + bn) * K + bc * 8]);
    cp_async16(smem + OFF_BLO + bn * SM_STRIDE + bc * 16, &Wlo[(size_t)(n0 + bn) * K + bc * 8]);
    asm volatile("cp.async.commit_group;" ::: "memory");
#pragma unroll
    for (int t = 0; t < 2; t++) {
        unsigned int h01, l01, h23, l23;
        bsplit2(stA[t].x, stA[t].y, h01, l01);
        bsplit2(stA[t].z, stA[t].w, h23, l23);
        *(uint2*)(smem + am[t] * SM_STRIDE + akq[t] * 8) = make_uint2(h01, h23);
        *(uint2*)(smem + OFF_ALO + am[t] * SM_STRIDE + akq[t] * 8) = make_uint2(l01, l23);
    }
    asm volatile("cp.async.wait_group 0;" ::: "memory");
    __syncthreads();

    int aRow = wm * 64 + ((lane >> 3) & 1) * 8 + (lane & 7);
    int aKb  = (lane >> 4) * 16;
    int l4 = lane & 15;
    int bRow = wn * 32 + (l4 & 7);
    int bKb  = (l4 >> 3) * 16;

    int buf = 0;
    for (int it = 0; it < niter; it++) {
        if (it + 1 < niter) {
#pragma unroll
            for (int t = 0; t < 2; t++)
                stA[t] = *(const float4*)&A[(size_t)(m0 + am[t]) * K + (it + 1) * GBK + akq[t] * 4];
            unsigned char* nb = smem + (buf ^ 1) * BUF_BYTES;
            cp_async16(nb + OFF_BHI + bn * SM_STRIDE + bc * 16,
                       &Whi[(size_t)(n0 + bn) * K + (it + 1) * GBK + bc * 8]);
            cp_async16(nb + OFF_BLO + bn * SM_STRIDE + bc * 16,
                       &Wlo[(size_t)(n0 + bn) * K + (it + 1) * GBK + bc * 8]);
            asm volatile("cp.async.commit_group;" ::: "memory");
        }

        unsigned int base = sbase + buf * BUF_BYTES;
        unsigned int aHi[4][4], aLo[4][4], bHi[4][2], bLo[4][2];
#pragma unroll
        for (int mt = 0; mt < 4; mt++) {
            unsigned int ra = base + (aRow + mt * 16) * SM_STRIDE + aKb;
            ldsm_x4(ra, aHi[mt]);
            ldsm_x4(ra + OFF_ALO, aLo[mt]);
        }
#pragma unroll
        for (int nt = 0; nt < 4; nt++) {
            unsigned int rb = base + OFF_BHI + (bRow + nt * 8) * SM_STRIDE + bKb;
            ldsm_x2(rb, bHi[nt]);
            ldsm_x2(rb + (OFF_BLO - OFF_BHI), bLo[nt]);
        }
#pragma unroll
        for (int mt = 0; mt < 4; mt++)
#pragma unroll
            for (int nt = 0; nt < 4; nt++) {
                mma_bf16(acc[mt][nt], aHi[mt], bHi[nt]);
                mma_bf16(acc[mt][nt], aHi[mt], bLo[nt]);
                mma_bf16(acc[mt][nt], aLo[mt], bHi[nt]);
            }

        if (it + 1 < niter) {
            unsigned char* nb = smem + (buf ^ 1) * BUF_BYTES;
#pragma unroll
            for (int t = 0; t < 2; t++) {
                unsigned int h01, l01, h23, l23;
                bsplit2(stA[t].x, stA[t].y, h01, l01);
                bsplit2(stA[t].z, stA[t].w, h23, l23);
                *(uint2*)(nb + am[t] * SM_STRIDE + akq[t] * 8) = make_uint2(h01, h23);
                *(uint2*)(nb + OFF_ALO + am[t] * SM_STRIDE + akq[t] * 8) = make_uint2(l01, l23);
            }
            asm volatile("cp.async.wait_group 0;" ::: "memory");
        }
        __syncthreads();
        buf ^= 1;
    }

    int cm = lane >> 2, cn = (lane & 3) * 2;
#pragma unroll
    for (int mt = 0; mt < 4; mt++) {
        int row = m0 + wm * 64 + mt * 16 + cm;
#pragma unroll
        for (int nt = 0; nt < 4; nt++) {
            int col = n0 + wn * 32 + nt * 8 + cn;
            *(__half2*)&out[(size_t)row * F + col] =
                __floats2half2_rn(acc[mt][nt][0], acc[mt][nt][1]);
            *(__half2*)&out[(size_t)(row + 8) * F + col] =
                __floats2half2_rn(acc[mt][nt][2], acc[mt][nt][3]);
        }
    }
}

// ---- scale hps by dis (in place): hps[row][*] *= dis[row] ------------------
__global__ __launch_bounds__(256) void scale_hps_kernel() {
    int idx = blockIdx.x * blockDim.x + threadIdx.x;   // one uint4 (8 halves)
    int row = idx >> 5;
    float d = g_dis[row];
    uint4 v = ((const uint4*)g_hps)[idx];
    __half2* h2 = (__half2*)&v;
#pragma unroll
    for (int q = 0; q < 4; q++) {
        float2 f = __half22float2(h2[q]);
        h2[q] = __floats2half2_rn(d * f.x, d * f.y);
    }
    ((uint4*)g_hps)[idx] = v;
}

// ---- GEMM2: A fp16 (exact), W fp16 hi/lo, 2 passes; out = fp16(dis*(A@W)) --
// Processes rows [mbase, mbase + gridDim.y*128). Writes a SEPARATE buffer.
__global__ __launch_bounds__(256) void gemm2_kernel(
    const __half* __restrict__ A,
    const unsigned short* __restrict__ Whi,
    const unsigned short* __restrict__ Wlo,
    __half* __restrict__ out, int K, int mbase)
{
    __shared__ __align__(16) unsigned char smem[2 * BUF2_BYTES];
    unsigned int sbase = (unsigned int)__cvta_generic_to_shared(smem);
    int tid = threadIdx.x, lane = tid & 31, wid = tid >> 5;
    int wm = wid & 1, wn = wid >> 1;
    int m0 = mbase + blockIdx.y * 128, n0 = blockIdx.x * 128;

    float acc[4][4][4];
#pragma unroll
    for (int i = 0; i < 4; i++)
#pragma unroll
        for (int j = 0; j < 4; j++)
#pragma unroll
            for (int q = 0; q < 4; q++) acc[i][j][q] = 0.f;

    int ar = tid >> 1, ac = tid & 1;
    int bn = tid >> 1, bc = tid & 1;
    const int niter = K / GBK;

    cp_async16(smem + ar * SM_STRIDE + ac * 16, &A[(size_t)(m0 + ar) * K + ac * 8]);
    cp_async16(smem + OFF2_BHI + bn * SM_STRIDE + bc * 16, &Whi[(size_t)(n0 + bn) * K + bc * 8]);
    cp_async16(smem + OFF2_BLO + bn * SM_STRIDE + bc * 16, &Wlo[(size_t)(n0 + bn) * K + bc * 8]);
    asm volatile("cp.async.commit_group;" ::: "memory");

    int aRow = wm * 64 + ((lane >> 3) & 1) * 8 + (lane & 7);
    int aKb  = (lane >> 4) * 16;
    int l4 = lane & 15;
    int bRow = wn * 32 + (l4 & 7);
    int bKb  = (l4 >> 3) * 16;

    int buf = 0;
    for (int it = 0; it < niter; it++) {
        if (it + 1 < niter) {
            unsigned char* nb = smem + (buf ^ 1) * BUF2_BYTES;
            cp_async16(nb + ar * SM_STRIDE + ac * 16,
                       &A[(size_t)(m0 + ar) * K + (it + 1) * GBK + ac * 8]);
            cp_async16(nb + OFF2_BHI + bn * SM_STRIDE + bc * 16,
                       &Whi[(size_t)(n0 + bn) * K + (it + 1) * GBK + bc * 8]);
            cp_async16(nb + OFF2_BLO + bn * SM_STRIDE + bc * 16,
                       &Wlo[(size_t)(n0 + bn) * K + (it + 1) * GBK + bc * 8]);
            asm volatile("cp.async.commit_group;" ::: "memory");
            asm volatile("cp.async.wait_group 1;" ::: "memory");
        } else {
            asm volatile("cp.async.wait_group 0;" ::: "memory");
        }
        __syncthreads();

        unsigned int base = sbase + buf * BUF2_BYTES;
        unsigned int aF[4][4], bHi[4][2], bLo[4][2];
#pragma unroll
        for (int mt = 0; mt < 4; mt++)
            ldsm_x4(base + (aRow + mt * 16) * SM_STRIDE + aKb, aF[mt]);
#pragma unroll
        for (int nt = 0; nt < 4; nt++) {
            unsigned int rb = base + OFF2_BHI + (bRow + nt * 8) * SM_STRIDE + bKb;
            ldsm_x2(rb, bHi[nt]);
            ldsm_x2(rb + (OFF2_BLO - OFF2_BHI), bLo[nt]);
        }
#pragma unroll
        for (int mt = 0; mt < 4; mt++)
#pragma unroll
            for (int nt = 0; nt < 4; nt++) {
                mma_f16(acc[mt][nt], aF[mt], bHi[nt]);
                mma_f16(acc[mt][nt], aF[mt], bLo[nt]);
            }
        __syncthreads();
        buf ^= 1;
    }

    int cm = lane >> 2, cn = (lane & 3) * 2;
#pragma unroll
    for (int mt = 0; mt < 4; mt++) {
        int row = m0 + wm * 64 + mt * 16 + cm;
        float d1 = g_dis[row], d2 = g_dis[row + 8];
#pragma unroll
        for (int nt = 0; nt < 4; nt++) {
            int col = n0 + wn * 32 + nt * 8 + cn;
            *(__half2*)&out[(size_t)row * F + col] =
                __floats2half2_rn(d1 * acc[mt][nt][0], d1 * acc[mt][nt][1]);
            *(__half2*)&out[(size_t)(row + 8) * F + col] =
                __floats2half2_rn(d2 * acc[mt][nt][2], d2 * acc[mt][nt][3]);
        }
    }
}

// ---------------- Aggregation: warp per destination node --------------------
__device__ __forceinline__ void acc8(float* a, uint4 v) {
    float2 f0 = __half22float2(*(__half2*)&v.x);
    float2 f1 = __half22float2(*(__half2*)&v.y);
    float2 f2 = __half22float2(*(__half2*)&v.z);
    float2 f3 = __half22float2(*(__half2*)&v.w);
    a[0] += f0.x; a[1] += f0.y; a[2] += f1.x; a[3] += f1.y;
    a[4] += f2.x; a[5] += f2.y; a[6] += f3.x; a[7] += f3.y;
}

__device__ __forceinline__ void agg_core(const __half* hp, const float* bias,
                                         int dst, int lane, float* r, int relu)
{
    const uint4* hp4 = (const uint4*)hp;
    float a[8];
    {
        uint4 v = hp4[(size_t)dst * 32 + lane];
        float2 f0 = __half22float2(*(__half2*)&v.x);
        float2 f1 = __half22float2(*(__half2*)&v.y);
        float2 f2 = __half22float2(*(__half2*)&v.z);
        float2 f3 = __half22float2(*(__half2*)&v.w);
        a[0] = f0.x; a[1] = f0.y; a[2] = f1.x; a[3] = f1.y;
        a[4] = f2.x; a[5] = f2.y; a[6] = f3.x; a[7] = f3.y;
    }
    int e = g_rowptr[dst], end = g_rowptr[dst + 1];
    for (; e + 4 <= end; e += 4) {
        int s0 = g_col[e], s1 = g_col[e + 1], s2 = g_col[e + 2], s3 = g_col[e + 3];
        uint4 v0 = hp4[(size_t)s0 * 32 + lane];
        uint4 v1 = hp4[(size_t)s1 * 32 + lane];
        uint4 v2 = hp4[(size_t)s2 * 32 + lane];
        uint4 v3 = hp4[(size_t)s3 * 32 + lane];
        acc8(a, v0); acc8(a, v1); acc8(a, v2); acc8(a, v3);
    }
    for (; e < end; e++) acc8(a, hp4[(size_t)g_col[e] * 32 + lane]);

    float dd = g_dis[dst];
    const float4* b4 = (const float4*)bias;
    float4 b0 = b4[lane * 2], b1 = b4[lane * 2 + 1];
    r[0] = fmaf(dd, a[0], b0.x); r[1] = fmaf(dd, a[1], b0.y);
    r[2] = fmaf(dd, a[2], b0.z); r[3] = fmaf(dd, a[3], b0.w);
    r[4] = fmaf(dd, a[4], b1.x); r[5] = fmaf(dd, a[5], b1.y);
    r[6] = fmaf(dd, a[6], b1.z); r[7] = fmaf(dd, a[7], b1.w);
    if (relu) {
#pragma unroll
        for (int j = 0; j < 8; j++) r[j] = fmaxf(r[j], 0.f);
    }
}

// agg1 chunk: nodes [nbase, nbase + 8*gridDim.x), fp16 output
__global__ __launch_bounds__(256) void agg_f16_kernel(
    const __half* __restrict__ hp, const float* __restrict__ bias,
    __half* __restrict__ out, int nbase)
{
    int dst = nbase + ((blockIdx.x * blockDim.x + threadIdx.x) >> 5);
    int lane = threadIdx.x & 31;
    float r[8];
    agg_core(hp, bias, dst, lane, r, 1);
    uint4 o;
    __half2* oh = (__half2*)&o;
    oh[0] = __floats2half2_rn(r[0], r[1]);
    oh[1] = __floats2half2_rn(r[2], r[3]);
    oh[2] = __floats2half2_rn(r[4], r[5]);
    oh[3] = __floats2half2_rn(r[6], r[7]);
    ((uint4*)out)[(size_t)dst * 32 + lane] = o;
}

// agg2 chunk: fp32 output
__global__ __launch_bounds__(256) void agg_f32_kernel(
    const __half* __restrict__ hp, const float* __restrict__ bias,
    float* __restrict__ out, int nbase)
{
    int dst = nbase + ((blockIdx.x * blockDim.x + threadIdx.x) >> 5);
    int lane = threadIdx.x & 31;
    float r[8];
    agg_core(hp, bias, dst, lane, r, 0);
    float4* o4 = (float4*)&out[(size_t)dst * F + lane * 8];
    o4[0] = make_float4(r[0], r[1], r[2], r[3]);
    o4[1] = make_float4(r[4], r[5], r[6], r[7]);
}

// ---------------- readout (meanmax) + final linear --------------------------
__global__ __launch_bounds__(256) void readout_kernel(
    const float* __restrict__ h, const float* __restrict__ Wm,
    const float* __restrict__ bm, float* __restrict__ out, int gbase)
{
    int g = gbase + blockIdx.x;
    int t = threadIdx.x;
    const float* base = h + (size_t)g * NODES_PER_G * F;
    float s = 0.f, mx = -INFINITY;
    for (int i = 0; i < NODES_PER_G; i++) {
        float v = base[(size_t)i * F + t];
        s += v;
        mx = fmaxf(mx, v);
    }
    __shared__ float gf[2 * F];
    gf[t]     = s * (1.0f / NODES_PER_G);
    gf[F + t] = mx;
    __syncthreads();

    float p0 = gf[t] * Wm[t * 2 + 0] + gf[F + t] * Wm[(F + t) * 2 + 0];
    float p1 = gf[t] * Wm[t * 2 + 1] + gf[F + t] * Wm[(F + t) * 2 + 1];
    __shared__ float r0[256], r1[256];
    r0[t] = p0; r1[t] = p1;
    __syncthreads();
    for (int off = 128; off > 0; off >>= 1) {
        if (t < off) { r0[t] += r0[t + off]; r1[t] += r1[t + off]; }
        __syncthreads();
    }
    if (t == 0) {
        out[g * 2 + 0] = r0[0] + bm[0];
        out[g * 2 + 1] = r1[0] + bm[1];
    }
}

// ---------------- launcher --------------------------------------------------
// fork 1: CSR build (s1) || wsplit+gemm1 (main)
// fork 2: agg1 chunks (main, read hps ONLY) -> gemm2 chunks (s1, write hps2 —
//         separate buffer, so later agg1 chunks still see intact hps).
//         agg2 chunks (s1, read hps2 after all gemm2) -> readout chunks (main).
extern "C" void kernel_launch(void* const* d_in, const int* in_sizes, int n_in,
                              void* d_out, int out_size)
{
    int base = (in_sizes[3] == 1) ? 4 : 3;
    const float* x  = (const float*)d_in[0];
    const void*  ei = d_in[1];
    const float* W1 = (const float*)d_in[base + 0];
    const float* b1 = (const float*)d_in[base + 1];
    const float* W2 = (const float*)d_in[base + 2];
    const float* b2 = (const float*)d_in[base + 3];
    const float* Wm = (const float*)d_in[base + 4];
    const float* bm = (const float*)d_in[base + 5];
    float* out = (float*)d_out;

    __half *hps, *p16, *hps2; float* buf;
    unsigned short *w1hi, *w1lo, *w2hi, *w2lo;
    int *degp, *curp;
    cudaGetSymbolAddress((void**)&hps,  g_hps);
    cudaGetSymbolAddress((void**)&p16,  g_p16);
    cudaGetSymbolAddress((void**)&hps2, g_hps2);
    cudaGetSymbolAddress((void**)&buf,  g_buf);
    cudaGetSymbolAddress((void**)&w1hi, g_w1hi);
    cudaGetSymbolAddress((void**)&w1lo, g_w1lo);
    cudaGetSymbolAddress((void**)&w2hi, g_w2hi);
    cudaGetSymbolAddress((void**)&w2lo, g_w2lo);
    cudaGetSymbolAddress((void**)&degp, g_deg);
    cudaGetSymbolAddress((void**)&curp, g_cursor);

    cudaStream_t s1;
    cudaStreamCreateWithFlags(&s1, cudaStreamNonBlocking);
    cudaEvent_t evFork, evJoin, evA[NCHUNKS], evB[NCHUNKS];
    cudaEventCreateWithFlags(&evFork, cudaEventDisableTiming);
    cudaEventCreateWithFlags(&evJoin, cudaEventDisableTiming);
    for (int i = 0; i < NCHUNKS; i++) {
        cudaEventCreateWithFlags(&evA[i], cudaEventDisableTiming);
        cudaEventCreateWithFlags(&evB[i], cudaEventDisableTiming);
    }

    const int TB = 256;
    dim3 gg1(2, N_TOTAL / 128);
    dim3 gg2(2, NODES_PER_CHUNK / 128);       // 2 x 200 per chunk
    int aggBlocks = NODES_PER_CHUNK / 8;      // 3200 per chunk

    // --- main stream prefix
    cudaMemsetAsync(degp, 0, N_TOTAL * sizeof(int), 0);
    cudaMemsetAsync(curp, 0, N_TOTAL * sizeof(int), 0);
    detect_kernel<<<1, 1024>>>((const unsigned int*)ei);
    cudaEventRecord(evFork, 0);

    // --- side stream: full CSR build
    cudaStreamWaitEvent(s1, evFork, 0);
    count_kernel<<<(E_TOTAL / 2 + TB - 1) / TB, TB, 0, s1>>>(ei);
    scan1_kernel<<<400, 256, 0, s1>>>();
    scan2_kernel<<<1, 512, 0, s1>>>();
    scan3_kernel<<<400, 256, 0, s1>>>();
    fill_kernel<<<(E_TOTAL / 2 + TB - 1) / TB, TB, 0, s1>>>(ei);
    cudaEventRecord(evJoin, s1);

    // --- main stream: weight prep + gemm1 overlap the whole CSR build
    wsplit_bf16_kernel<<<(400 * 256 + TB - 1) / TB, TB>>>(W1, 400, w1hi, w1lo);
    wsplit_f16_kernel<<<(256 * 256 + TB - 1) / TB, TB>>>(W2, 256, w2hi, w2lo);
    gemm1_kernel<<<gg1, 256>>>(x, w1hi, w1lo, hps, 400);  // hps = fp16(x@W1)
    cudaStreamWaitEvent(0, evJoin, 0);                    // need dis + CSR
    scale_hps_kernel<<<N_TOTAL * 32 / TB, TB>>>();        // hps *= dis[row]

    // --- pipeline: agg1 chunks (main, hps->p16) -> gemm2 chunks (s1, p16->hps2)
    for (int i = 0; i < NCHUNKS; i++) {
        agg_f16_kernel<<<aggBlocks, 256>>>(hps, b1, p16, i * NODES_PER_CHUNK);
        cudaEventRecord(evA[i], 0);
        cudaStreamWaitEvent(s1, evA[i], 0);
        gemm2_kernel<<<gg2, 256, 0, s1>>>(p16, w2hi, w2lo, hps2, 256,
                                          i * NODES_PER_CHUNK);
    }
    // --- agg2 chunks on s1 (stream order: after all gemm2), hps2 -> buf;
    //     readout chunks on main stream per-chunk (buf rows are chunk-local)
    for (int i = 0; i < NCHUNKS; i++) {
        agg_f32_kernel<<<aggBlocks, 256, 0, s1>>>(hps2, b2, buf,
                                                  i * NODES_PER_CHUNK);
        cudaEventRecord(evB[i], s1);
        cudaStreamWaitEvent(0, evB[i], 0);
        readout_kernel<<<GRAPHS_PER_CHUNK, 256>>>(buf, Wm, bm, out,
                                                  i * GRAPHS_PER_CHUNK);
    }
}

// round 13
// speedup vs baseline: 1.0941x; 1.0941x over previous
#include <cuda_runtime.h>
#include <cuda_bf16.h>
#include <cuda_fp16.h>
#include <math.h>

#define N_TOTAL 102400
#define E_TOTAL 4096000
#define F 256
#define NODES_PER_G 400
#define NUM_G 256

// ---------------- scratch (device globals; no allocation allowed) -----------
__device__ int   g_deg[N_TOTAL];
__device__ int   g_cursor[N_TOTAL];
__device__ int   g_rowptr[N_TOTAL + 1];
__device__ int   g_boff[401];
__device__ int   g_col[E_TOTAL];
__device__ float g_dis[N_TOTAL];
__device__ __half g_hps[(size_t)N_TOTAL * F];   // gemm out / agg in (both layers)
__device__ __half g_p16[(size_t)N_TOTAL * F];   // agg1 out / gemm2 in
__device__ float  g_buf[(size_t)N_TOTAL * F];   // agg2 out (fp32) / readout in
__device__ int   g_is64;
// W1 pre-split bf16 hi/lo, transposed [256][400]; W2 fp16 [256][256]
__device__ unsigned short g_w1hi[256 * 400];
__device__ unsigned short g_w1lo[256 * 400];
__device__ unsigned short g_w2f[256 * 256];

__device__ __forceinline__ void cp_async16(void* smem_dst, const void* gmem_src) {
    unsigned long long sa = __cvta_generic_to_shared(smem_dst);
    asm volatile("cp.async.cg.shared.global [%0], [%1], 16;"
                 :: "l"(sa), "l"(gmem_src) : "memory");
}

// ---------------- setup kernels --------------------------------------------
__global__ void detect_kernel(const unsigned int* __restrict__ w) {
    __shared__ int any;
    if (threadIdx.x == 0) any = 0;
    __syncthreads();
    int idx = 1 + 2 * (int)threadIdx.x;
    if (w[idx] != 0u) atomicOr(&any, 1);
    __syncthreads();
    if (threadIdx.x == 0) g_is64 = (any ? 0 : 1);
}

__global__ void count_kernel(const void* __restrict__ ei) {
    int t = blockIdx.x * blockDim.x + threadIdx.x;
    if (t * 2 >= E_TOTAL) return;
    if (g_is64) {
        longlong2 d = ((const longlong2*)((const long long*)ei + E_TOTAL))[t];
        atomicAdd(&g_deg[(int)d.x], 1);
        atomicAdd(&g_deg[(int)d.y], 1);
    } else {
        int2 d = ((const int2*)((const int*)ei + E_TOTAL))[t];
        atomicAdd(&g_deg[d.x], 1);
        atomicAdd(&g_deg[d.y], 1);
    }
}

__global__ void scan1_kernel() {
    __shared__ int s[256];
    int b = blockIdx.x, tid = threadIdx.x;
    int i = b * 256 + tid;
    int d = g_deg[i];
    g_dis[i] = rsqrtf((float)(d + 1));
    s[tid] = d;
    __syncthreads();
#pragma unroll
    for (int off = 1; off < 256; off <<= 1) {
        int t = 0;
        if (tid >= off) t = s[tid - off];
        __syncthreads();
        s[tid] += t;
        __syncthreads();
    }
    g_rowptr[i] = s[tid] - d;
    if (tid == 255) g_boff[b] = s[255];
}

__global__ void scan2_kernel() {
    __shared__ int s[512];
    int tid = threadIdx.x;
    int v = (tid < 400) ? g_boff[tid] : 0;
    s[tid] = v;
    __syncthreads();
#pragma unroll
    for (int off = 1; off < 512; off <<= 1) {
        int t = 0;
        if (tid >= off) t = s[tid - off];
        __syncthreads();
        s[tid] += t;
        __syncthreads();
    }
    if (tid <= 400) g_boff[tid] = s[tid] - v;
}

__global__ void scan3_kernel() {
    int b = blockIdx.x, tid = threadIdx.x;
    int i = b * 256 + tid;
    g_rowptr[i] += g_boff[b];
    if (i == N_TOTAL - 1) g_rowptr[N_TOTAL] = g_boff[400];
}

__global__ void fill_kernel(const void* __restrict__ ei) {
    int t = blockIdx.x * blockDim.x + threadIdx.x;
    if (t * 2 >= E_TOTAL) return;
    int s0, s1, d0, d1;
    if (g_is64) {
        longlong2 s = ((const longlong2*)ei)[t];
        longlong2 d = ((const longlong2*)((const long long*)ei + E_TOTAL))[t];
        s0 = (int)s.x; s1 = (int)s.y; d0 = (int)d.x; d1 = (int)d.y;
    } else {
        int2 s = ((const int2*)ei)[t];
        int2 d = ((const int2*)((const int*)ei + E_TOTAL))[t];
        s0 = s.x; s1 = s.y; d0 = d.x; d1 = d.y;
    }
    int p0 = atomicAdd(&g_cursor[d0], 1);
    g_col[g_rowptr[d0] + p0] = s0;
    int p1 = atomicAdd(&g_cursor[d1], 1);
    g_col[g_rowptr[d1] + p1] = s1;
}

// ---------------- weight prep kernels ----------------------------------------
__global__ void wsplit_bf16_kernel(const float* __restrict__ W, int K,
                                   unsigned short* __restrict__ hi,
                                   unsigned short* __restrict__ lo) {
    int idx = blockIdx.x * blockDim.x + threadIdx.x;
    if (idx >= K * 256) return;
    int n = idx / K, k = idx % K;
    float a = W[(size_t)k * 256 + n];
    __nv_bfloat16 h = __float2bfloat16_rn(a);
    float hf = __bfloat162float(h);
    __nv_bfloat16 l = __float2bfloat16_rn(a - hf);
    hi[(size_t)n * K + k] = __bfloat16_as_ushort(h);
    lo[(size_t)n * K + k] = __bfloat16_as_ushort(l);
}

// W2: plain fp16 convert + transpose (single-pass gemm2)
__global__ void wconv_f16_kernel(const float* __restrict__ W, int K,
                                 unsigned short* __restrict__ hi) {
    int idx = blockIdx.x * blockDim.x + threadIdx.x;
    if (idx >= K * 256) return;
    int n = idx / K, k = idx % K;
    hi[(size_t)n * K + k] = __half_as_ushort(__float2half_rn(W[(size_t)k * 256 + n]));
}

// ---------------- shared GEMM machinery -------------------------------------
#define GBK 16
#define SM_STRIDE 48
// gemm1 (bf16x3): A-hi, A-lo, B-hi, B-lo  (4 x 6144)
#define BUF_BYTES 24576
#define OFF_ALO 6144
#define OFF_BHI 12288
#define OFF_BLO 18432
// gemm2 (fp16x1): A, B  (2 x 6144)
#define BUF2_BYTES 12288
#define OFF2_B 6144

__device__ __forceinline__ void bsplit2(float a0, float a1,
                                        unsigned int& hi, unsigned int& lo) {
    __nv_bfloat16 h0 = __float2bfloat16_rn(a0);
    __nv_bfloat16 h1 = __float2bfloat16_rn(a1);
    float f0 = __bfloat162float(h0), f1 = __bfloat162float(h1);
    __nv_bfloat16 l0 = __float2bfloat16_rn(a0 - f0);
    __nv_bfloat16 l1 = __float2bfloat16_rn(a1 - f1);
    hi = (unsigned int)__bfloat16_as_ushort(h0) |
         ((unsigned int)__bfloat16_as_ushort(h1) << 16);
    lo = (unsigned int)__bfloat16_as_ushort(l0) |
         ((unsigned int)__bfloat16_as_ushort(l1) << 16);
}

__device__ __forceinline__ void ldsm_x4(unsigned int addr, unsigned int* r) {
    asm volatile("ldmatrix.sync.aligned.m8n8.x4.shared.b16 {%0,%1,%2,%3}, [%4];"
                 : "=r"(r[0]), "=r"(r[1]), "=r"(r[2]), "=r"(r[3]) : "r"(addr));
}
__device__ __forceinline__ void ldsm_x2(unsigned int addr, unsigned int* r) {
    asm volatile("ldmatrix.sync.aligned.m8n8.x2.shared.b16 {%0,%1}, [%2];"
                 : "=r"(r[0]), "=r"(r[1]) : "r"(addr));
}
__device__ __forceinline__ void mma_bf16(float* c, const unsigned int* a,
                                         const unsigned int* b) {
    asm volatile(
        "mma.sync.aligned.m16n8k16.row.col.f32.bf16.bf16.f32 "
        "{%0,%1,%2,%3}, {%4,%5,%6,%7}, {%8,%9}, {%0,%1,%2,%3};"
        : "+f"(c[0]), "+f"(c[1]), "+f"(c[2]), "+f"(c[3])
        : "r"(a[0]), "r"(a[1]), "r"(a[2]), "r"(a[3]), "r"(b[0]), "r"(b[1]));
}
__device__ __forceinline__ void mma_f16(float* c, const unsigned int* a,
                                        const unsigned int* b) {
    asm volatile(
        "mma.sync.aligned.m16n8k16.row.col.f32.f16.f16.f32 "
        "{%0,%1,%2,%3}, {%4,%5,%6,%7}, {%8,%9}, {%0,%1,%2,%3};"
        : "+f"(c[0]), "+f"(c[1]), "+f"(c[2]), "+f"(c[3])
        : "r"(a[0]), "r"(a[1]), "r"(a[2]), "r"(a[3]), "r"(b[0]), "r"(b[1]));
}

// ---- GEMM1: A fp32, W bf16 hi/lo, 3 passes; out = fp16(A@W)  (NO dis) ------
__global__ __launch_bounds__(256) void gemm1_kernel(
    const float* __restrict__ A,
    const unsigned short* __restrict__ Whi,
    const unsigned short* __restrict__ Wlo,
    __half* __restrict__ out, int K)
{
    __shared__ __align__(16) unsigned char smem[2 * BUF_BYTES];
    unsigned int sbase = (unsigned int)__cvta_generic_to_shared(smem);
    int tid = threadIdx.x, lane = tid & 31, wid = tid >> 5;
    int wm = wid & 1, wn = wid >> 1;
    int m0 = blockIdx.y * 128, n0 = blockIdx.x * 128;

    float acc[4][4][4];
#pragma unroll
    for (int i = 0; i < 4; i++)
#pragma unroll
        for (int j = 0; j < 4; j++)
#pragma unroll
            for (int q = 0; q < 4; q++) acc[i][j][q] = 0.f;

    int am[2], akq[2];
    am[0] = tid >> 2;           akq[0] = tid & 3;
    am[1] = (tid + 256) >> 2;   akq[1] = (tid + 256) & 3;
    int bn = tid >> 1, bc = tid & 1;

    const int niter = K / GBK;
    float4 stA[2];

#pragma unroll
    for (int t = 0; t < 2; t++)
        stA[t] = *(const float4*)&A[(size_t)(m0 + am[t]) * K + akq[t] * 4];
    cp_async16(smem + OFF_BHI + bn * SM_STRIDE + bc * 16, &Whi[(size_t)(n0 + bn) * K + bc * 8]);
    cp_async16(smem + OFF_BLO + bn * SM_STRIDE + bc * 16, &Wlo[(size_t)(n0 + bn) * K + bc * 8]);
    asm volatile("cp.async.commit_group;" ::: "memory");
#pragma unroll
    for (int t = 0; t < 2; t++) {
        unsigned int h01, l01, h23, l23;
        bsplit2(stA[t].x, stA[t].y, h01, l01);
        bsplit2(stA[t].z, stA[t].w, h23, l23);
        *(uint2*)(smem + am[t] * SM_STRIDE + akq[t] * 8) = make_uint2(h01, h23);
        *(uint2*)(smem + OFF_ALO + am[t] * SM_STRIDE + akq[t] * 8) = make_uint2(l01, l23);
    }
    asm volatile("cp.async.wait_group 0;" ::: "memory");
    __syncthreads();

    int aRow = wm * 64 + ((lane >> 3) & 1) * 8 + (lane & 7);
    int aKb  = (lane >> 4) * 16;
    int l4 = lane & 15;
    int bRow = wn * 32 + (l4 & 7);
    int bKb  = (l4 >> 3) * 16;

    int buf = 0;
    for (int it = 0; it < niter; it++) {
        if (it + 1 < niter) {
#pragma unroll
            for (int t = 0; t < 2; t++)
                stA[t] = *(const float4*)&A[(size_t)(m0 + am[t]) * K + (it + 1) * GBK + akq[t] * 4];
            unsigned char* nb = smem + (buf ^ 1) * BUF_BYTES;
            cp_async16(nb + OFF_BHI + bn * SM_STRIDE + bc * 16,
                       &Whi[(size_t)(n0 + bn) * K + (it + 1) * GBK + bc * 8]);
            cp_async16(nb + OFF_BLO + bn * SM_STRIDE + bc * 16,
                       &Wlo[(size_t)(n0 + bn) * K + (it + 1) * GBK + bc * 8]);
            asm volatile("cp.async.commit_group;" ::: "memory");
        }

        unsigned int base = sbase + buf * BUF_BYTES;
        unsigned int aHi[4][4], aLo[4][4], bHi[4][2], bLo[4][2];
#pragma unroll
        for (int mt = 0; mt < 4; mt++) {
            unsigned int ra = base + (aRow + mt * 16) * SM_STRIDE + aKb;
            ldsm_x4(ra, aHi[mt]);
            ldsm_x4(ra + OFF_ALO, aLo[mt]);
        }
#pragma unroll
        for (int nt = 0; nt < 4; nt++) {
            unsigned int rb = base + OFF_BHI + (bRow + nt * 8) * SM_STRIDE + bKb;
            ldsm_x2(rb, bHi[nt]);
            ldsm_x2(rb + (OFF_BLO - OFF_BHI), bLo[nt]);
        }
#pragma unroll
        for (int mt = 0; mt < 4; mt++)
#pragma unroll
            for (int nt = 0; nt < 4; nt++) {
                mma_bf16(acc[mt][nt], aHi[mt], bHi[nt]);
                mma_bf16(acc[mt][nt], aHi[mt], bLo[nt]);
                mma_bf16(acc[mt][nt], aLo[mt], bHi[nt]);
            }

        if (it + 1 < niter) {
            unsigned char* nb = smem + (buf ^ 1) * BUF_BYTES;
#pragma unroll
            for (int t = 0; t < 2; t++) {
                unsigned int h01, l01, h23, l23;
                bsplit2(stA[t].x, stA[t].y, h01, l01);
                bsplit2(stA[t].z, stA[t].w, h23, l23);
                *(uint2*)(nb + am[t] * SM_STRIDE + akq[t] * 8) = make_uint2(h01, h23);
                *(uint2*)(nb + OFF_ALO + am[t] * SM_STRIDE + akq[t] * 8) = make_uint2(l01, l23);
            }
            asm volatile("cp.async.wait_group 0;" ::: "memory");
        }
        __syncthreads();
        buf ^= 1;
    }

    int cm = lane >> 2, cn = (lane & 3) * 2;
#pragma unroll
    for (int mt = 0; mt < 4; mt++) {
        int row = m0 + wm * 64 + mt * 16 + cm;
#pragma unroll
        for (int nt = 0; nt < 4; nt++) {
            int col = n0 + wn * 32 + nt * 8 + cn;
            *(__half2*)&out[(size_t)row * F + col] =
                __floats2half2_rn(acc[mt][nt][0], acc[mt][nt][1]);
            *(__half2*)&out[(size_t)(row + 8) * F + col] =
                __floats2half2_rn(acc[mt][nt][2], acc[mt][nt][3]);
        }
    }
}

// ---- GEMM2: A fp16, W fp16, single pass; out = fp16(dis[m]*(A@W)) ----------
__global__ __launch_bounds__(256) void gemm2_kernel(
    const __half* __restrict__ A,
    const unsigned short* __restrict__ Wf,
    __half* __restrict__ out, int K)
{
    __shared__ __align__(16) unsigned char smem[2 * BUF2_BYTES];
    unsigned int sbase = (unsigned int)__cvta_generic_to_shared(smem);
    int tid = threadIdx.x, lane = tid & 31, wid = tid >> 5;
    int wm = wid & 1, wn = wid >> 1;
    int m0 = blockIdx.y * 128, n0 = blockIdx.x * 128;

    float acc[4][4][4];
#pragma unroll
    for (int i = 0; i < 4; i++)
#pragma unroll
        for (int j = 0; j < 4; j++)
#pragma unroll
            for (int q = 0; q < 4; q++) acc[i][j][q] = 0.f;

    int ar = tid >> 1, ac = tid & 1;
    const int niter = K / GBK;

    cp_async16(smem + ar * SM_STRIDE + ac * 16, &A[(size_t)(m0 + ar) * K + ac * 8]);
    cp_async16(smem + OFF2_B + ar * SM_STRIDE + ac * 16, &Wf[(size_t)(n0 + ar) * K + ac * 8]);
    asm volatile("cp.async.commit_group;" ::: "memory");

    int aRow = wm * 64 + ((lane >> 3) & 1) * 8 + (lane & 7);
    int aKb  = (lane >> 4) * 16;
    int l4 = lane & 15;
    int bRow = wn * 32 + (l4 & 7);
    int bKb  = (l4 >> 3) * 16;

    int buf = 0;
    for (int it = 0; it < niter; it++) {
        if (it + 1 < niter) {
            unsigned char* nb = smem + (buf ^ 1) * BUF2_BYTES;
            cp_async16(nb + ar * SM_STRIDE + ac * 16,
                       &A[(size_t)(m0 + ar) * K + (it + 1) * GBK + ac * 8]);
            cp_async16(nb + OFF2_B + ar * SM_STRIDE + ac * 16,
                       &Wf[(size_t)(n0 + ar) * K + (it + 1) * GBK + ac * 8]);
            asm volatile("cp.async.commit_group;" ::: "memory");
            asm volatile("cp.async.wait_group 1;" ::: "memory");
        } else {
            asm volatile("cp.async.wait_group 0;" ::: "memory");
        }
        __syncthreads();

        unsigned int base = sbase + buf * BUF2_BYTES;
        unsigned int aF[4][4], bF[4][2];
#pragma unroll
        for (int mt = 0; mt < 4; mt++)
            ldsm_x4(base + (aRow + mt * 16) * SM_STRIDE + aKb, aF[mt]);
#pragma unroll
        for (int nt = 0; nt < 4; nt++)
            ldsm_x2(base + OFF2_B + (bRow + nt * 8) * SM_STRIDE + bKb, bF[nt]);
#pragma unroll
        for (int mt = 0; mt < 4; mt++)
#pragma unroll
            for (int nt = 0; nt < 4; nt++)
                mma_f16(acc[mt][nt], aF[mt], bF[nt]);
        __syncthreads();
        buf ^= 1;
    }

    int cm = lane >> 2, cn = (lane & 3) * 2;
#pragma unroll
    for (int mt = 0; mt < 4; mt++) {
        int row = m0 + wm * 64 + mt * 16 + cm;
        float d1 = g_dis[row], d2 = g_dis[row + 8];
#pragma unroll
        for (int nt = 0; nt < 4; nt++) {
            int col = n0 + wn * 32 + nt * 8 + cn;
            *(__half2*)&out[(size_t)row * F + col] =
                __floats2half2_rn(d1 * acc[mt][nt][0], d1 * acc[mt][nt][1]);
            *(__half2*)&out[(size_t)(row + 8) * F + col] =
                __floats2half2_rn(d2 * acc[mt][nt][2], d2 * acc[mt][nt][3]);
        }
    }
}

// ---------------- Aggregation ------------------------------------------------
__device__ __forceinline__ void acc8w(float* a, uint4 v, float w) {
    float2 f0 = __half22float2(*(__half2*)&v.x);
    float2 f1 = __half22float2(*(__half2*)&v.y);
    float2 f2 = __half22float2(*(__half2*)&v.z);
    float2 f3 = __half22float2(*(__half2*)&v.w);
    a[0] = fmaf(w, f0.x, a[0]); a[1] = fmaf(w, f0.y, a[1]);
    a[2] = fmaf(w, f1.x, a[2]); a[3] = fmaf(w, f1.y, a[3]);
    a[4] = fmaf(w, f2.x, a[4]); a[5] = fmaf(w, f2.y, a[5]);
    a[6] = fmaf(w, f3.x, a[6]); a[7] = fmaf(w, f3.y, a[7]);
}
__device__ __forceinline__ void acc8(float* a, uint4 v) {
    float2 f0 = __half22float2(*(__half2*)&v.x);
    float2 f1 = __half22float2(*(__half2*)&v.y);
    float2 f2 = __half22float2(*(__half2*)&v.z);
    float2 f3 = __half22float2(*(__half2*)&v.w);
    a[0] += f0.x; a[1] += f0.y; a[2] += f1.x; a[3] += f1.y;
    a[4] += f2.x; a[5] += f2.y; a[6] += f3.x; a[7] += f3.y;
}

// agg1: weighted gather (dis[src] folded here — no scale_hps pass),
// out16[dst] = fp16(relu(dis[dst]*(sum dis[s]*hps[s] + dis[dst]*hps[dst]) + b))
__global__ __launch_bounds__(256) void agg1_kernel(
    const __half* __restrict__ hp, const float* __restrict__ bias,
    __half* __restrict__ out)
{
    int dst = (blockIdx.x * blockDim.x + threadIdx.x) >> 5;
    if (dst >= N_TOTAL) return;
    int lane = threadIdx.x & 31;
    const uint4* hp4 = (const uint4*)hp;
    float dd = g_dis[dst];

    float a[8] = {0.f, 0.f, 0.f, 0.f, 0.f, 0.f, 0.f, 0.f};
    acc8w(a, hp4[(size_t)dst * 32 + lane], dd);   // self loop

    int e = g_rowptr[dst], end = g_rowptr[dst + 1];
    for (; e + 4 <= end; e += 4) {
        int s0 = g_col[e], s1 = g_col[e + 1], s2 = g_col[e + 2], s3 = g_col[e + 3];
        float w0 = g_dis[s0], w1 = g_dis[s1], w2 = g_dis[s2], w3 = g_dis[s3];
        uint4 v0 = hp4[(size_t)s0 * 32 + lane];
        uint4 v1 = hp4[(size_t)s1 * 32 + lane];
        uint4 v2 = hp4[(size_t)s2 * 32 + lane];
        uint4 v3 = hp4[(size_t)s3 * 32 + lane];
        acc8w(a, v0, w0); acc8w(a, v1, w1); acc8w(a, v2, w2); acc8w(a, v3, w3);
    }
    for (; e < end; e++) {
        int s0 = g_col[e];
        acc8w(a, hp4[(size_t)s0 * 32 + lane], g_dis[s0]);
    }

    const float4* b4 = (const float4*)bias;
    float4 b0 = b4[lane * 2], b1 = b4[lane * 2 + 1];
    float r[8];
    r[0] = fmaxf(fmaf(dd, a[0], b0.x), 0.f); r[1] = fmaxf(fmaf(dd, a[1], b0.y), 0.f);
    r[2] = fmaxf(fmaf(dd, a[2], b0.z), 0.f); r[3] = fmaxf(fmaf(dd, a[3], b0.w), 0.f);
    r[4] = fmaxf(fmaf(dd, a[4], b1.x), 0.f); r[5] = fmaxf(fmaf(dd, a[5], b1.y), 0.f);
    r[6] = fmaxf(fmaf(dd, a[6], b1.z), 0.f); r[7] = fmaxf(fmaf(dd, a[7], b1.w), 0.f);
    uint4 o;
    __half2* oh = (__half2*)&o;
    oh[0] = __floats2half2_rn(r[0], r[1]);
    oh[1] = __floats2half2_rn(r[2], r[3]);
    oh[2] = __floats2half2_rn(r[4], r[5]);
    oh[3] = __floats2half2_rn(r[6], r[7]);
    ((uint4*)out)[(size_t)dst * 32 + lane] = o;
}

// agg2: plain gather (dis[src] prefolded by gemm2 epilogue), fp32 out
__global__ __launch_bounds__(256) void agg2_kernel(
    const __half* __restrict__ hp, const float* __restrict__ bias,
    float* __restrict__ out)
{
    int dst = (blockIdx.x * blockDim.x + threadIdx.x) >> 5;
    if (dst >= N_TOTAL) return;
    int lane = threadIdx.x & 31;
    const uint4* hp4 = (const uint4*)hp;

    float a[8];
    {
        uint4 v = hp4[(size_t)dst * 32 + lane];
        float2 f0 = __half22float2(*(__half2*)&v.x);
        float2 f1 = __half22float2(*(__half2*)&v.y);
        float2 f2 = __half22float2(*(__half2*)&v.z);
        float2 f3 = __half22float2(*(__half2*)&v.w);
        a[0] = f0.x; a[1] = f0.y; a[2] = f1.x; a[3] = f1.y;
        a[4] = f2.x; a[5] = f2.y; a[6] = f3.x; a[7] = f3.y;
    }
    int e = g_rowptr[dst], end = g_rowptr[dst + 1];
    for (; e + 4 <= end; e += 4) {
        int s0 = g_col[e], s1 = g_col[e + 1], s2 = g_col[e + 2], s3 = g_col[e + 3];
        uint4 v0 = hp4[(size_t)s0 * 32 + lane];
        uint4 v1 = hp4[(size_t)s1 * 32 + lane];
        uint4 v2 = hp4[(size_t)s2 * 32 + lane];
        uint4 v3 = hp4[(size_t)s3 * 32 + lane];
        acc8(a, v0); acc8(a, v1); acc8(a, v2); acc8(a, v3);
    }
    for (; e < end; e++) acc8(a, hp4[(size_t)g_col[e] * 32 + lane]);

    float dd = g_dis[dst];
    const float4* b4 = (const float4*)bias;
    float4 b0 = b4[lane * 2], b1 = b4[lane * 2 + 1];
    float4* o4 = (float4*)&out[(size_t)dst * F + lane * 8];
    o4[0] = make_float4(fmaf(dd, a[0], b0.x), fmaf(dd, a[1], b0.y),
                        fmaf(dd, a[2], b0.z), fmaf(dd, a[3], b0.w));
    o4[1] = make_float4(fmaf(dd, a[4], b1.x), fmaf(dd, a[5], b1.y),
                        fmaf(dd, a[6], b1.z), fmaf(dd, a[7], b1.w));
}

// ---------------- readout (meanmax) + final linear --------------------------
__global__ __launch_bounds__(256) void readout_kernel(
    const float* __restrict__ h, const float* __restrict__ Wm,
    const float* __restrict__ bm, float* __restrict__ out)
{
    int g = blockIdx.x;
    int t = threadIdx.x;
    const float* base = h + (size_t)g * NODES_PER_G * F;
    float s = 0.f, mx = -INFINITY;
    for (int i = 0; i < NODES_PER_G; i++) {
        float v = base[(size_t)i * F + t];
        s += v;
        mx = fmaxf(mx, v);
    }
    __shared__ float gf[2 * F];
    gf[t]     = s * (1.0f / NODES_PER_G);
    gf[F + t] = mx;
    __syncthreads();

    float p0 = gf[t] * Wm[t * 2 + 0] + gf[F + t] * Wm[(F + t) * 2 + 0];
    float p1 = gf[t] * Wm[t * 2 + 1] + gf[F + t] * Wm[(F + t) * 2 + 1];
    __shared__ float r0[256], r1[256];
    r0[t] = p0; r1[t] = p1;
    __syncthreads();
    for (int off = 128; off > 0; off >>= 1) {
        if (t < off) { r0[t] += r0[t + off]; r1[t] += r1[t + off]; }
        __syncthreads();
    }
    if (t == 0) {
        out[g * 2 + 0] = r0[0] + bm[0];
        out[g * 2 + 1] = r1[0] + bm[1];
    }
}

// ---------------- launcher --------------------------------------------------
// ONE side stream (R9/R11-proven resource pattern — passes the harness memory
// tracker; the second stream in R12 tripped a 2MB driver allocation).
//   s1:   CSR build (count/scan/fill) after detect
//   main: memsets, detect, wsplits, gemm1 (overlaps CSR), [join]
//         agg1 -> gemm2 -> agg2 -> readout (serial: agg owns the L2)
extern "C" void kernel_launch(void* const* d_in, const int* in_sizes, int n_in,
                              void* d_out, int out_size)
{
    int base = (in_sizes[3] == 1) ? 4 : 3;
    const float* x  = (const float*)d_in[0];
    const void*  ei = d_in[1];
    const float* W1 = (const float*)d_in[base + 0];
    const float* b1 = (const float*)d_in[base + 1];
    const float* W2 = (const float*)d_in[base + 2];
    const float* b2 = (const float*)d_in[base + 3];
    const float* Wm = (const float*)d_in[base + 4];
    const float* bm = (const float*)d_in[base + 5];
    float* out = (float*)d_out;

    __half *hps, *p16; float* buf;
    unsigned short *w1hi, *w1lo, *w2f;
    int *degp, *curp;
    cudaGetSymbolAddress((void**)&hps,  g_hps);
    cudaGetSymbolAddress((void**)&p16,  g_p16);
    cudaGetSymbolAddress((void**)&buf,  g_buf);
    cudaGetSymbolAddress((void**)&w1hi, g_w1hi);
    cudaGetSymbolAddress((void**)&w1lo, g_w1lo);
    cudaGetSymbolAddress((void**)&w2f,  g_w2f);
    cudaGetSymbolAddress((void**)&degp, g_deg);
    cudaGetSymbolAddress((void**)&curp, g_cursor);

    cudaStream_t s1;
    cudaStreamCreateWithFlags(&s1, cudaStreamNonBlocking);
    cudaEvent_t evFork, evJoin;
    cudaEventCreateWithFlags(&evFork, cudaEventDisableTiming);
    cudaEventCreateWithFlags(&evJoin, cudaEventDisableTiming);

    const int TB = 256;
    dim3 gg(2, N_TOTAL / 128);

    // --- main prefix
    cudaMemsetAsync(degp, 0, N_TOTAL * sizeof(int), 0);
    cudaMemsetAsync(curp, 0, N_TOTAL * sizeof(int), 0);
    detect_kernel<<<1, 1024>>>((const unsigned int*)ei);
    cudaEventRecord(evFork, 0);

    // --- side stream: full CSR build
    cudaStreamWaitEvent(s1, evFork, 0);
    count_kernel<<<(E_TOTAL / 2 + TB - 1) / TB, TB, 0, s1>>>(ei);
    scan1_kernel<<<400, 256, 0, s1>>>();
    scan2_kernel<<<1, 512, 0, s1>>>();
    scan3_kernel<<<400, 256, 0, s1>>>();
    fill_kernel<<<(E_TOTAL / 2 + TB - 1) / TB, TB, 0, s1>>>(ei);
    cudaEventRecord(evJoin, s1);

    // --- main: weight prep + gemm1 overlap the CSR build
    wsplit_bf16_kernel<<<(400 * 256 + TB - 1) / TB, TB>>>(W1, 400, w1hi, w1lo);
    wconv_f16_kernel<<<(256 * 256 + TB - 1) / TB, TB>>>(W2, 256, w2f);
    gemm1_kernel<<<gg, 256>>>(x, w1hi, w1lo, hps, 400);   // hps = fp16(x@W1)
    cudaStreamWaitEvent(0, evJoin, 0);                    // need dis + CSR
    // serial back half — agg kernels own the L2
    agg1_kernel<<<N_TOTAL / 8, 256>>>(hps, b1, p16);      // weighted gather + relu
    gemm2_kernel<<<gg, 256>>>(p16, w2f, hps, 256);        // hps = fp16(dis*(p16@W2))
    agg2_kernel<<<N_TOTAL / 8, 256>>>(hps, b2, buf);      // plain gather, fp32
    readout_kernel<<<NUM_G, 256>>>(buf, Wm, bm, out);
}

// round 14
// speedup vs baseline: 1.1803x; 1.0789x over previous
#include <cuda_runtime.h>
#include <cuda_bf16.h>
#include <cuda_fp16.h>
#include <math.h>

#define N_TOTAL 102400
#define E_TOTAL 4096000
#define F 256
#define NODES_PER_G 400
#define NUM_G 256

// ---------------- scratch (device globals; no allocation allowed) -----------
__device__ int   g_deg[N_TOTAL];
__device__ int   g_cursor[N_TOTAL];
__device__ int   g_rowptr[N_TOTAL + 1];
__device__ int   g_boff[401];
__device__ int   g_col[E_TOTAL];
__device__ float g_dis[N_TOTAL];
__device__ __half g_hps[(size_t)N_TOTAL * F];   // gemm out / agg in (both layers)
__device__ __half g_p16[(size_t)N_TOTAL * F];   // agg1 out / gemm2 in
__device__ float  g_buf[(size_t)N_TOTAL * F];   // agg2 out (fp32) / readout in
__device__ int   g_is64;
// W1 fp16 hi/lo, transposed [256][400]; W2 fp16 [256][256]
__device__ unsigned short g_w1hi[256 * 400];
__device__ unsigned short g_w1lo[256 * 400];
__device__ unsigned short g_w2f[256 * 256];

__device__ __forceinline__ void cp_async16(void* smem_dst, const void* gmem_src) {
    unsigned long long sa = __cvta_generic_to_shared(smem_dst);
    asm volatile("cp.async.cg.shared.global [%0], [%1], 16;"
                 :: "l"(sa), "l"(gmem_src) : "memory");
}

// ---------------- setup kernels --------------------------------------------
__global__ void detect_kernel(const unsigned int* __restrict__ w) {
    __shared__ int any;
    if (threadIdx.x == 0) any = 0;
    __syncthreads();
    int idx = 1 + 2 * (int)threadIdx.x;
    if (w[idx] != 0u) atomicOr(&any, 1);
    __syncthreads();
    if (threadIdx.x == 0) g_is64 = (any ? 0 : 1);
}

__global__ void count_kernel(const void* __restrict__ ei) {
    int t = blockIdx.x * blockDim.x + threadIdx.x;
    if (t * 2 >= E_TOTAL) return;
    if (g_is64) {
        longlong2 d = ((const longlong2*)((const long long*)ei + E_TOTAL))[t];
        atomicAdd(&g_deg[(int)d.x], 1);
        atomicAdd(&g_deg[(int)d.y], 1);
    } else {
        int2 d = ((const int2*)((const int*)ei + E_TOTAL))[t];
        atomicAdd(&g_deg[d.x], 1);
        atomicAdd(&g_deg[d.y], 1);
    }
}

__global__ void scan1_kernel() {
    __shared__ int s[256];
    int b = blockIdx.x, tid = threadIdx.x;
    int i = b * 256 + tid;
    int d = g_deg[i];
    g_dis[i] = rsqrtf((float)(d + 1));
    s[tid] = d;
    __syncthreads();
#pragma unroll
    for (int off = 1; off < 256; off <<= 1) {
        int t = 0;
        if (tid >= off) t = s[tid - off];
        __syncthreads();
        s[tid] += t;
        __syncthreads();
    }
    g_rowptr[i] = s[tid] - d;
    if (tid == 255) g_boff[b] = s[255];
}

__global__ void scan2_kernel() {
    __shared__ int s[512];
    int tid = threadIdx.x;
    int v = (tid < 400) ? g_boff[tid] : 0;
    s[tid] = v;
    __syncthreads();
#pragma unroll
    for (int off = 1; off < 512; off <<= 1) {
        int t = 0;
        if (tid >= off) t = s[tid - off];
        __syncthreads();
        s[tid] += t;
        __syncthreads();
    }
    if (tid <= 400) g_boff[tid] = s[tid] - v;
}

__global__ void scan3_kernel() {
    int b = blockIdx.x, tid = threadIdx.x;
    int i = b * 256 + tid;
    g_rowptr[i] += g_boff[b];
    if (i == N_TOTAL - 1) g_rowptr[N_TOTAL] = g_boff[400];
}

__global__ void fill_kernel(const void* __restrict__ ei) {
    int t = blockIdx.x * blockDim.x + threadIdx.x;
    if (t * 2 >= E_TOTAL) return;
    int s0, s1, d0, d1;
    if (g_is64) {
        longlong2 s = ((const longlong2*)ei)[t];
        longlong2 d = ((const longlong2*)((const long long*)ei + E_TOTAL))[t];
        s0 = (int)s.x; s1 = (int)s.y; d0 = (int)d.x; d1 = (int)d.y;
    } else {
        int2 s = ((const int2*)ei)[t];
        int2 d = ((const int2*)((const int*)ei + E_TOTAL))[t];
        s0 = s.x; s1 = s.y; d0 = d.x; d1 = d.y;
    }
    int p0 = atomicAdd(&g_cursor[d0], 1);
    g_col[g_rowptr[d0] + p0] = s0;
    int p1 = atomicAdd(&g_cursor[d1], 1);
    g_col[g_rowptr[d1] + p1] = s1;
}

// ---------------- weight prep kernels ----------------------------------------
// W1: fp16 hi/lo split + transpose (2-pass gemm1; exact to ~2^-22)
__global__ void wsplit_f16_kernel(const float* __restrict__ W, int K,
                                  unsigned short* __restrict__ hi,
                                  unsigned short* __restrict__ lo) {
    int idx = blockIdx.x * blockDim.x + threadIdx.x;
    if (idx >= K * 256) return;
    int n = idx / K, k = idx % K;
    float a = W[(size_t)k * 256 + n];
    __half h = __float2half_rn(a);
    __half l = __float2half_rn(a - __half2float(h));
    hi[(size_t)n * K + k] = __half_as_ushort(h);
    lo[(size_t)n * K + k] = __half_as_ushort(l);
}

// W2: plain fp16 convert + transpose (single-pass gemm2)
__global__ void wconv_f16_kernel(const float* __restrict__ W, int K,
                                 unsigned short* __restrict__ hi) {
    int idx = blockIdx.x * blockDim.x + threadIdx.x;
    if (idx >= K * 256) return;
    int n = idx / K, k = idx % K;
    hi[(size_t)n * K + k] = __half_as_ushort(__float2half_rn(W[(size_t)k * 256 + n]));
}

// ---------------- shared GEMM machinery -------------------------------------
#define GBK 16
#define SM_STRIDE 48
// gemm1 (A fp16, W fp16 hi/lo): A, B-hi, B-lo  (3 x 6144)
#define BUF1_BYTES 18432
#define OFF1_BHI 6144
#define OFF1_BLO 12288
// gemm2 (fp16x1): A, B  (2 x 6144)
#define BUF2_BYTES 12288
#define OFF2_B 6144

__device__ __forceinline__ uint4 f32x8_to_h8(float4 a, float4 b) {
    uint4 r;
    __half2* p = (__half2*)&r;
    p[0] = __floats2half2_rn(a.x, a.y);
    p[1] = __floats2half2_rn(a.z, a.w);
    p[2] = __floats2half2_rn(b.x, b.y);
    p[3] = __floats2half2_rn(b.z, b.w);
    return r;
}

__device__ __forceinline__ void ldsm_x4(unsigned int addr, unsigned int* r) {
    asm volatile("ldmatrix.sync.aligned.m8n8.x4.shared.b16 {%0,%1,%2,%3}, [%4];"
                 : "=r"(r[0]), "=r"(r[1]), "=r"(r[2]), "=r"(r[3]) : "r"(addr));
}
__device__ __forceinline__ void ldsm_x2(unsigned int addr, unsigned int* r) {
    asm volatile("ldmatrix.sync.aligned.m8n8.x2.shared.b16 {%0,%1}, [%2];"
                 : "=r"(r[0]), "=r"(r[1]) : "r"(addr));
}
__device__ __forceinline__ void mma_f16(float* c, const unsigned int* a,
                                        const unsigned int* b) {
    asm volatile(
        "mma.sync.aligned.m16n8k16.row.col.f32.f16.f16.f32 "
        "{%0,%1,%2,%3}, {%4,%5,%6,%7}, {%8,%9}, {%0,%1,%2,%3};"
        : "+f"(c[0]), "+f"(c[1]), "+f"(c[2]), "+f"(c[3])
        : "r"(a[0]), "r"(a[1]), "r"(a[2]), "r"(a[3]), "r"(b[0]), "r"(b[1]));
}

// ---- GEMM1: A fp32->fp16 on the fly, W fp16 hi/lo, 2 MMAs/k; out=fp16(A@W) -
__global__ __launch_bounds__(256) void gemm1_kernel(
    const float* __restrict__ A,
    const unsigned short* __restrict__ Whi,
    const unsigned short* __restrict__ Wlo,
    __half* __restrict__ out, int K)
{
    __shared__ __align__(16) unsigned char smem[2 * BUF1_BYTES];
    unsigned int sbase = (unsigned int)__cvta_generic_to_shared(smem);
    int tid = threadIdx.x, lane = tid & 31, wid = tid >> 5;
    int wm = wid & 1, wn = wid >> 1;
    int m0 = blockIdx.y * 128, n0 = blockIdx.x * 128;

    float acc[4][4][4];
#pragma unroll
    for (int i = 0; i < 4; i++)
#pragma unroll
        for (int j = 0; j < 4; j++)
#pragma unroll
            for (int q = 0; q < 4; q++) acc[i][j][q] = 0.f;

    int ar = tid >> 1, ac = tid & 1;      // row 0..127, 8-col chunk 0..1
    const int niter = K / GBK;
    float4 stA0, stA1;

    // prologue: tile 0
    stA0 = *(const float4*)&A[(size_t)(m0 + ar) * K + ac * 8];
    stA1 = *(const float4*)&A[(size_t)(m0 + ar) * K + ac * 8 + 4];
    cp_async16(smem + OFF1_BHI + ar * SM_STRIDE + ac * 16, &Whi[(size_t)(n0 + ar) * K + ac * 8]);
    cp_async16(smem + OFF1_BLO + ar * SM_STRIDE + ac * 16, &Wlo[(size_t)(n0 + ar) * K + ac * 8]);
    asm volatile("cp.async.commit_group;" ::: "memory");
    *(uint4*)(smem + ar * SM_STRIDE + ac * 16) = f32x8_to_h8(stA0, stA1);
    asm volatile("cp.async.wait_group 0;" ::: "memory");
    __syncthreads();

    int aRow = wm * 64 + ((lane >> 3) & 1) * 8 + (lane & 7);
    int aKb  = (lane >> 4) * 16;
    int l4 = lane & 15;
    int bRow = wn * 32 + (l4 & 7);
    int bKb  = (l4 >> 3) * 16;

    int buf = 0;
    for (int it = 0; it < niter; it++) {
        if (it + 1 < niter) {
            stA0 = *(const float4*)&A[(size_t)(m0 + ar) * K + (it + 1) * GBK + ac * 8];
            stA1 = *(const float4*)&A[(size_t)(m0 + ar) * K + (it + 1) * GBK + ac * 8 + 4];
            unsigned char* nb = smem + (buf ^ 1) * BUF1_BYTES;
            cp_async16(nb + OFF1_BHI + ar * SM_STRIDE + ac * 16,
                       &Whi[(size_t)(n0 + ar) * K + (it + 1) * GBK + ac * 8]);
            cp_async16(nb + OFF1_BLO + ar * SM_STRIDE + ac * 16,
                       &Wlo[(size_t)(n0 + ar) * K + (it + 1) * GBK + ac * 8]);
            asm volatile("cp.async.commit_group;" ::: "memory");
        }

        unsigned int base = sbase + buf * BUF1_BYTES;
        unsigned int aF[4][4], bHi[4][2], bLo[4][2];
#pragma unroll
        for (int mt = 0; mt < 4; mt++)
            ldsm_x4(base + (aRow + mt * 16) * SM_STRIDE + aKb, aF[mt]);
#pragma unroll
        for (int nt = 0; nt < 4; nt++) {
            unsigned int rb = base + OFF1_BHI + (bRow + nt * 8) * SM_STRIDE + bKb;
            ldsm_x2(rb, bHi[nt]);
            ldsm_x2(rb + (OFF1_BLO - OFF1_BHI), bLo[nt]);
        }
#pragma unroll
        for (int mt = 0; mt < 4; mt++)
#pragma unroll
            for (int nt = 0; nt < 4; nt++) {
                mma_f16(acc[mt][nt], aF[mt], bHi[nt]);
                mma_f16(acc[mt][nt], aF[mt], bLo[nt]);
            }

        if (it + 1 < niter) {
            unsigned char* nb = smem + (buf ^ 1) * BUF1_BYTES;
            *(uint4*)(nb + ar * SM_STRIDE + ac * 16) = f32x8_to_h8(stA0, stA1);
            asm volatile("cp.async.wait_group 0;" ::: "memory");
        }
        __syncthreads();
        buf ^= 1;
    }

    int cm = lane >> 2, cn = (lane & 3) * 2;
#pragma unroll
    for (int mt = 0; mt < 4; mt++) {
        int row = m0 + wm * 64 + mt * 16 + cm;
#pragma unroll
        for (int nt = 0; nt < 4; nt++) {
            int col = n0 + wn * 32 + nt * 8 + cn;
            *(__half2*)&out[(size_t)row * F + col] =
                __floats2half2_rn(acc[mt][nt][0], acc[mt][nt][1]);
            *(__half2*)&out[(size_t)(row + 8) * F + col] =
                __floats2half2_rn(acc[mt][nt][2], acc[mt][nt][3]);
        }
    }
}

// ---- GEMM2: A fp16, W fp16, single pass; out = fp16(dis[m]*(A@W)) ----------
__global__ __launch_bounds__(256) void gemm2_kernel(
    const __half* __restrict__ A,
    const unsigned short* __restrict__ Wf,
    __half* __restrict__ out, int K)
{
    __shared__ __align__(16) unsigned char smem[2 * BUF2_BYTES];
    unsigned int sbase = (unsigned int)__cvta_generic_to_shared(smem);
    int tid = threadIdx.x, lane = tid & 31, wid = tid >> 5;
    int wm = wid & 1, wn = wid >> 1;
    int m0 = blockIdx.y * 128, n0 = blockIdx.x * 128;

    float acc[4][4][4];
#pragma unroll
    for (int i = 0; i < 4; i++)
#pragma unroll
        for (int j = 0; j < 4; j++)
#pragma unroll
            for (int q = 0; q < 4; q++) acc[i][j][q] = 0.f;

    int ar = tid >> 1, ac = tid & 1;
    const int niter = K / GBK;

    cp_async16(smem + ar * SM_STRIDE + ac * 16, &A[(size_t)(m0 + ar) * K + ac * 8]);
    cp_async16(smem + OFF2_B + ar * SM_STRIDE + ac * 16, &Wf[(size_t)(n0 + ar) * K + ac * 8]);
    asm volatile("cp.async.commit_group;" ::: "memory");

    int aRow = wm * 64 + ((lane >> 3) & 1) * 8 + (lane & 7);
    int aKb  = (lane >> 4) * 16;
    int l4 = lane & 15;
    int bRow = wn * 32 + (l4 & 7);
    int bKb  = (l4 >> 3) * 16;

    int buf = 0;
    for (int it = 0; it < niter; it++) {
        if (it + 1 < niter) {
            unsigned char* nb = smem + (buf ^ 1) * BUF2_BYTES;
            cp_async16(nb + ar * SM_STRIDE + ac * 16,
                       &A[(size_t)(m0 + ar) * K + (it + 1) * GBK + ac * 8]);
            cp_async16(nb + OFF2_B + ar * SM_STRIDE + ac * 16,
                       &Wf[(size_t)(n0 + ar) * K + (it + 1) * GBK + ac * 8]);
            asm volatile("cp.async.commit_group;" ::: "memory");
            asm volatile("cp.async.wait_group 1;" ::: "memory");
        } else {
            asm volatile("cp.async.wait_group 0;" ::: "memory");
        }
        __syncthreads();

        unsigned int base = sbase + buf * BUF2_BYTES;
        unsigned int aF[4][4], bF[4][2];
#pragma unroll
        for (int mt = 0; mt < 4; mt++)
            ldsm_x4(base + (aRow + mt * 16) * SM_STRIDE + aKb, aF[mt]);
#pragma unroll
        for (int nt = 0; nt < 4; nt++)
            ldsm_x2(base + OFF2_B + (bRow + nt * 8) * SM_STRIDE + bKb, bF[nt]);
#pragma unroll
        for (int mt = 0; mt < 4; mt++)
#pragma unroll
            for (int nt = 0; nt < 4; nt++)
                mma_f16(acc[mt][nt], aF[mt], bF[nt]);
        __syncthreads();
        buf ^= 1;
    }

    int cm = lane >> 2, cn = (lane & 3) * 2;
#pragma unroll
    for (int mt = 0; mt < 4; mt++) {
        int row = m0 + wm * 64 + mt * 16 + cm;
        float d1 = g_dis[row], d2 = g_dis[row + 8];
#pragma unroll
        for (int nt = 0; nt < 4; nt++) {
            int col = n0 + wn * 32 + nt * 8 + cn;
            *(__half2*)&out[(size_t)row * F + col] =
                __floats2half2_rn(d1 * acc[mt][nt][0], d1 * acc[mt][nt][1]);
            *(__half2*)&out[(size_t)(row + 8) * F + col] =
                __floats2half2_rn(d2 * acc[mt][nt][2], d2 * acc[mt][nt][3]);
        }
    }
}

// ---------------- Aggregation ------------------------------------------------
__device__ __forceinline__ void acc8w(float* a, uint4 v, float w) {
    float2 f0 = __half22float2(*(__half2*)&v.x);
    float2 f1 = __half22float2(*(__half2*)&v.y);
    float2 f2 = __half22float2(*(__half2*)&v.z);
    float2 f3 = __half22float2(*(__half2*)&v.w);
    a[0] = fmaf(w, f0.x, a[0]); a[1] = fmaf(w, f0.y, a[1]);
    a[2] = fmaf(w, f1.x, a[2]); a[3] = fmaf(w, f1.y, a[3]);
    a[4] = fmaf(w, f2.x, a[4]); a[5] = fmaf(w, f2.y, a[5]);
    a[6] = fmaf(w, f3.x, a[6]); a[7] = fmaf(w, f3.y, a[7]);
}
__device__ __forceinline__ void acc8(float* a, uint4 v) {
    float2 f0 = __half22float2(*(__half2*)&v.x);
    float2 f1 = __half22float2(*(__half2*)&v.y);
    float2 f2 = __half22float2(*(__half2*)&v.z);
    float2 f3 = __half22float2(*(__half2*)&v.w);
    a[0] += f0.x; a[1] += f0.y; a[2] += f1.x; a[3] += f1.y;
    a[4] += f2.x; a[5] += f2.y; a[6] += f3.x; a[7] += f3.y;
}

// agg1: weighted gather (dis[src] folded here),
// out16[dst] = fp16(relu(dis[dst]*(sum dis[s]*hps[s] + dis[dst]*hps[dst]) + b))
__global__ __launch_bounds__(256) void agg1_kernel(
    const __half* __restrict__ hp, const float* __restrict__ bias,
    __half* __restrict__ out)
{
    int dst = (blockIdx.x * blockDim.x + threadIdx.x) >> 5;
    if (dst >= N_TOTAL) return;
    int lane = threadIdx.x & 31;
    const uint4* hp4 = (const uint4*)hp;
    float dd = g_dis[dst];

    float a[8] = {0.f, 0.f, 0.f, 0.f, 0.f, 0.f, 0.f, 0.f};
    acc8w(a, hp4[(size_t)dst * 32 + lane], dd);   // self loop

    int e = g_rowptr[dst], end = g_rowptr[dst + 1];
    for (; e + 4 <= end; e += 4) {
        int s0 = g_col[e], s1 = g_col[e + 1], s2 = g_col[e + 2], s3 = g_col[e + 3];
        float w0 = g_dis[s0], w1 = g_dis[s1], w2 = g_dis[s2], w3 = g_dis[s3];
        uint4 v0 = hp4[(size_t)s0 * 32 + lane];
        uint4 v1 = hp4[(size_t)s1 * 32 + lane];
        uint4 v2 = hp4[(size_t)s2 * 32 + lane];
        uint4 v3 = hp4[(size_t)s3 * 32 + lane];
        acc8w(a, v0, w0); acc8w(a, v1, w1); acc8w(a, v2, w2); acc8w(a, v3, w3);
    }
    for (; e < end; e++) {
        int s0 = g_col[e];
        acc8w(a, hp4[(size_t)s0 * 32 + lane], g_dis[s0]);
    }

    const float4* b4 = (const float4*)bias;
    float4 b0 = b4[lane * 2], b1 = b4[lane * 2 + 1];
    float r[8];
    r[0] = fmaxf(fmaf(dd, a[0], b0.x), 0.f); r[1] = fmaxf(fmaf(dd, a[1], b0.y), 0.f);
    r[2] = fmaxf(fmaf(dd, a[2], b0.z), 0.f); r[3] = fmaxf(fmaf(dd, a[3], b0.w), 0.f);
    r[4] = fmaxf(fmaf(dd, a[4], b1.x), 0.f); r[5] = fmaxf(fmaf(dd, a[5], b1.y), 0.f);
    r[6] = fmaxf(fmaf(dd, a[6], b1.z), 0.f); r[7] = fmaxf(fmaf(dd, a[7], b1.w), 0.f);
    uint4 o;
    __half2* oh = (__half2*)&o;
    oh[0] = __floats2half2_rn(r[0], r[1]);
    oh[1] = __floats2half2_rn(r[2], r[3]);
    oh[2] = __floats2half2_rn(r[4], r[5]);
    oh[3] = __floats2half2_rn(r[6], r[7]);
    ((uint4*)out)[(size_t)dst * 32 + lane] = o;
}

// agg2: plain gather (dis[src] prefolded by gemm2 epilogue), fp32 out
__global__ __launch_bounds__(256) void agg2_kernel(
    const __half* __restrict__ hp, const float* __restrict__ bias,
    float* __restrict__ out)
{
    int dst = (blockIdx.x * blockDim.x + threadIdx.x) >> 5;
    if (dst >= N_TOTAL) return;
    int lane = threadIdx.x & 31;
    const uint4* hp4 = (const uint4*)hp;

    float a[8];
    {
        uint4 v = hp4[(size_t)dst * 32 + lane];
        float2 f0 = __half22float2(*(__half2*)&v.x);
        float2 f1 = __half22float2(*(__half2*)&v.y);
        float2 f2 = __half22float2(*(__half2*)&v.z);
        float2 f3 = __half22float2(*(__half2*)&v.w);
        a[0] = f0.x; a[1] = f0.y; a[2] = f1.x; a[3] = f1.y;
        a[4] = f2.x; a[5] = f2.y; a[6] = f3.x; a[7] = f3.y;
    }
    int e = g_rowptr[dst], end = g_rowptr[dst + 1];
    for (; e + 4 <= end; e += 4) {
        int s0 = g_col[e], s1 = g_col[e + 1], s2 = g_col[e + 2], s3 = g_col[e + 3];
        uint4 v0 = hp4[(size_t)s0 * 32 + lane];
        uint4 v1 = hp4[(size_t)s1 * 32 + lane];
        uint4 v2 = hp4[(size_t)s2 * 32 + lane];
        uint4 v3 = hp4[(size_t)s3 * 32 + lane];
        acc8(a, v0); acc8(a, v1); acc8(a, v2); acc8(a, v3);
    }
    for (; e < end; e++) acc8(a, hp4[(size_t)g_col[e] * 32 + lane]);

    float dd = g_dis[dst];
    const float4* b4 = (const float4*)bias;
    float4 b0 = b4[lane * 2], b1 = b4[lane * 2 + 1];
    float4* o4 = (float4*)&out[(size_t)dst * F + lane * 8];
    o4[0] = make_float4(fmaf(dd, a[0], b0.x), fmaf(dd, a[1], b0.y),
                        fmaf(dd, a[2], b0.z), fmaf(dd, a[3], b0.w));
    o4[1] = make_float4(fmaf(dd, a[4], b1.x), fmaf(dd, a[5], b1.y),
                        fmaf(dd, a[6], b1.z), fmaf(dd, a[7], b1.w));
}

// ---------------- readout (meanmax) + final linear --------------------------
__global__ __launch_bounds__(256) void readout_kernel(
    const float* __restrict__ h, const float* __restrict__ Wm,
    const float* __restrict__ bm, float* __restrict__ out)
{
    int g = blockIdx.x;
    int t = threadIdx.x;
    const float* base = h + (size_t)g * NODES_PER_G * F;
    float s = 0.f, mx = -INFINITY;
    for (int i = 0; i < NODES_PER_G; i++) {
        float v = base[(size_t)i * F + t];
        s += v;
        mx = fmaxf(mx, v);
    }
    __shared__ float gf[2 * F];
    gf[t]     = s * (1.0f / NODES_PER_G);
    gf[F + t] = mx;
    __syncthreads();

    float p0 = gf[t] * Wm[t * 2 + 0] + gf[F + t] * Wm[(F + t) * 2 + 0];
    float p1 = gf[t] * Wm[t * 2 + 1] + gf[F + t] * Wm[(F + t) * 2 + 1];
    __shared__ float r0[256], r1[256];
    r0[t] = p0; r1[t] = p1;
    __syncthreads();
    for (int off = 128; off > 0; off >>= 1) {
        if (t < off) { r0[t] += r0[t + off]; r1[t] += r1[t + off]; }
        __syncthreads();
    }
    if (t == 0) {
        out[g * 2 + 0] = r0[0] + bm[0];
        out[g * 2 + 1] = r1[0] + bm[1];
    }
}

// ---------------- launcher --------------------------------------------------
// ONE side stream (harness-proven resource pattern).
//   s1:   CSR build (count/scan/fill) after detect
//   main: memsets, detect, wsplits, gemm1 (overlaps CSR), [join]
//         agg1 -> gemm2 -> agg2 -> readout (serial: agg owns the L2)
extern "C" void kernel_launch(void* const* d_in, const int* in_sizes, int n_in,
                              void* d_out, int out_size)
{
    int base = (in_sizes[3] == 1) ? 4 : 3;
    const float* x  = (const float*)d_in[0];
    const void*  ei = d_in[1];
    const float* W1 = (const float*)d_in[base + 0];
    const float* b1 = (const float*)d_in[base + 1];
    const float* W2 = (const float*)d_in[base + 2];
    const float* b2 = (const float*)d_in[base + 3];
    const float* Wm = (const float*)d_in[base + 4];
    const float* bm = (const float*)d_in[base + 5];
    float* out = (float*)d_out;

    __half *hps, *p16; float* buf;
    unsigned short *w1hi, *w1lo, *w2f;
    int *degp, *curp;
    cudaGetSymbolAddress((void**)&hps,  g_hps);
    cudaGetSymbolAddress((void**)&p16,  g_p16);
    cudaGetSymbolAddress((void**)&buf,  g_buf);
    cudaGetSymbolAddress((void**)&w1hi, g_w1hi);
    cudaGetSymbolAddress((void**)&w1lo, g_w1lo);
    cudaGetSymbolAddress((void**)&w2f,  g_w2f);
    cudaGetSymbolAddress((void**)&degp, g_deg);
    cudaGetSymbolAddress((void**)&curp, g_cursor);

    cudaStream_t s1;
    cudaStreamCreateWithFlags(&s1, cudaStreamNonBlocking);
    cudaEvent_t evFork, evJoin;
    cudaEventCreateWithFlags(&evFork, cudaEventDisableTiming);
    cudaEventCreateWithFlags(&evJoin, cudaEventDisableTiming);

    const int TB = 256;
    dim3 gg(2, N_TOTAL / 128);

    // --- main prefix
    cudaMemsetAsync(degp, 0, N_TOTAL * sizeof(int), 0);
    cudaMemsetAsync(curp, 0, N_TOTAL * sizeof(int), 0);
    detect_kernel<<<1, 1024>>>((const unsigned int*)ei);
    cudaEventRecord(evFork, 0);

    // --- side stream: full CSR build
    cudaStreamWaitEvent(s1, evFork, 0);
    count_kernel<<<(E_TOTAL / 2 + TB - 1) / TB, TB, 0, s1>>>(ei);
    scan1_kernel<<<400, 256, 0, s1>>>();
    scan2_kernel<<<1, 512, 0, s1>>>();
    scan3_kernel<<<400, 256, 0, s1>>>();
    fill_kernel<<<(E_TOTAL / 2 + TB - 1) / TB, TB, 0, s1>>>(ei);
    cudaEventRecord(evJoin, s1);

    // --- main: weight prep + gemm1 overlap the CSR build
    wsplit_f16_kernel<<<(400 * 256 + TB - 1) / TB, TB>>>(W1, 400, w1hi, w1lo);
    wconv_f16_kernel<<<(256 * 256 + TB - 1) / TB, TB>>>(W2, 256, w2f);
    gemm1_kernel<<<gg, 256>>>(x, w1hi, w1lo, hps, 400);   // hps = fp16(x@W1)
    cudaStreamWaitEvent(0, evJoin, 0);                    // need dis + CSR
    // serial back half — agg kernels own the L2
    agg1_kernel<<<N_TOTAL / 8, 256>>>(hps, b1, p16);      // weighted gather + relu
    gemm2_kernel<<<gg, 256>>>(p16, w2f, hps, 256);        // hps = fp16(dis*(p16@W2))
    agg2_kernel<<<N_TOTAL / 8, 256>>>(hps, b2, buf);      // plain gather, fp32
    readout_kernel<<<NUM_G, 256>>>(buf, Wm, bm, out);
}

// round 15
// speedup vs baseline: 1.1849x; 1.0038x over previous
#include <cuda_runtime.h>
#include <cuda_bf16.h>
#include <cuda_fp16.h>
#include <math.h>

#define N_TOTAL 102400
#define E_TOTAL 4096000
#define F 256
#define NODES_PER_G 400
#define NUM_G 256

// ---------------- scratch (device globals; no allocation allowed) -----------
__device__ int   g_deg[N_TOTAL];
__device__ int   g_cursor[N_TOTAL];
__device__ int   g_rowptr[N_TOTAL + 1];
__device__ int   g_boff[401];
__device__ int   g_col[E_TOTAL];
__device__ float g_dis[N_TOTAL];
__device__ __half g_hps[(size_t)N_TOTAL * F];   // gemm out / agg in (both layers)
__device__ __half g_p16[(size_t)N_TOTAL * F];   // agg1 out / gemm2 in; REUSED: agg2 out / readout in
__device__ int   g_is64;
// W1 fp16 hi/lo, transposed [256][400]; W2 fp16 [256][256]
__device__ unsigned short g_w1hi[256 * 400];
__device__ unsigned short g_w1lo[256 * 400];
__device__ unsigned short g_w2f[256 * 256];

__device__ __forceinline__ void cp_async16(void* smem_dst, const void* gmem_src) {
    unsigned long long sa = __cvta_generic_to_shared(smem_dst);
    asm volatile("cp.async.cg.shared.global [%0], [%1], 16;"
                 :: "l"(sa), "l"(gmem_src) : "memory");
}

// ---------------- setup kernels --------------------------------------------
__global__ void detect_kernel(const unsigned int* __restrict__ w) {
    __shared__ int any;
    if (threadIdx.x == 0) any = 0;
    __syncthreads();
    int idx = 1 + 2 * (int)threadIdx.x;
    if (w[idx] != 0u) atomicOr(&any, 1);
    __syncthreads();
    if (threadIdx.x == 0) g_is64 = (any ? 0 : 1);
}

__global__ void count_kernel(const void* __restrict__ ei) {
    int t = blockIdx.x * blockDim.x + threadIdx.x;
    if (t * 2 >= E_TOTAL) return;
    if (g_is64) {
        longlong2 d = ((const longlong2*)((const long long*)ei + E_TOTAL))[t];
        atomicAdd(&g_deg[(int)d.x], 1);
        atomicAdd(&g_deg[(int)d.y], 1);
    } else {
        int2 d = ((const int2*)((const int*)ei + E_TOTAL))[t];
        atomicAdd(&g_deg[d.x], 1);
        atomicAdd(&g_deg[d.y], 1);
    }
}

__global__ void scan1_kernel() {
    __shared__ int s[256];
    int b = blockIdx.x, tid = threadIdx.x;
    int i = b * 256 + tid;
    int d = g_deg[i];
    g_dis[i] = rsqrtf((float)(d + 1));
    s[tid] = d;
    __syncthreads();
#pragma unroll
    for (int off = 1; off < 256; off <<= 1) {
        int t = 0;
        if (tid >= off) t = s[tid - off];
        __syncthreads();
        s[tid] += t;
        __syncthreads();
    }
    g_rowptr[i] = s[tid] - d;
    if (tid == 255) g_boff[b] = s[255];
}

__global__ void scan2_kernel() {
    __shared__ int s[512];
    int tid = threadIdx.x;
    int v = (tid < 400) ? g_boff[tid] : 0;
    s[tid] = v;
    __syncthreads();
#pragma unroll
    for (int off = 1; off < 512; off <<= 1) {
        int t = 0;
        if (tid >= off) t = s[tid - off];
        __syncthreads();
        s[tid] += t;
        __syncthreads();
    }
    if (tid <= 400) g_boff[tid] = s[tid] - v;
}

__global__ void scan3_kernel() {
    int b = blockIdx.x, tid = threadIdx.x;
    int i = b * 256 + tid;
    g_rowptr[i] += g_boff[b];
    if (i == N_TOTAL - 1) g_rowptr[N_TOTAL] = g_boff[400];
}

__global__ void fill_kernel(const void* __restrict__ ei) {
    int t = blockIdx.x * blockDim.x + threadIdx.x;
    if (t * 2 >= E_TOTAL) return;
    int s0, s1, d0, d1;
    if (g_is64) {
        longlong2 s = ((const longlong2*)ei)[t];
        longlong2 d = ((const longlong2*)((const long long*)ei + E_TOTAL))[t];
        s0 = (int)s.x; s1 = (int)s.y; d0 = (int)d.x; d1 = (int)d.y;
    } else {
        int2 s = ((const int2*)ei)[t];
        int2 d = ((const int2*)((const int*)ei + E_TOTAL))[t];
        s0 = s.x; s1 = s.y; d0 = d.x; d1 = d.y;
    }
    int p0 = atomicAdd(&g_cursor[d0], 1);
    g_col[g_rowptr[d0] + p0] = s0;
    int p1 = atomicAdd(&g_cursor[d1], 1);
    g_col[g_rowptr[d1] + p1] = s1;
}

// ---------------- weight prep kernels ----------------------------------------
// W1: fp16 hi/lo split + transpose (2-pass gemm1; exact to ~2^-22)
__global__ void wsplit_f16_kernel(const float* __restrict__ W, int K,
                                  unsigned short* __restrict__ hi,
                                  unsigned short* __restrict__ lo) {
    int idx = blockIdx.x * blockDim.x + threadIdx.x;
    if (idx >= K * 256) return;
    int n = idx / K, k = idx % K;
    float a = W[(size_t)k * 256 + n];
    __half h = __float2half_rn(a);
    __half l = __float2half_rn(a - __half2float(h));
    hi[(size_t)n * K + k] = __half_as_ushort(h);
    lo[(size_t)n * K + k] = __half_as_ushort(l);
}

// W2: plain fp16 convert + transpose (single-pass gemm2)
__global__ void wconv_f16_kernel(const float* __restrict__ W, int K,
                                 unsigned short* __restrict__ hi) {
    int idx = blockIdx.x * blockDim.x + threadIdx.x;
    if (idx >= K * 256) return;
    int n = idx / K, k = idx % K;
    hi[(size_t)n * K + k] = __half_as_ushort(__float2half_rn(W[(size_t)k * 256 + n]));
}

// ---------------- shared GEMM machinery -------------------------------------
#define GBK 16
#define SM_STRIDE 48
// gemm1 (A fp16, W fp16 hi/lo): A, B-hi, B-lo  (3 x 6144)
#define BUF1_BYTES 18432
#define OFF1_BHI 6144
#define OFF1_BLO 12288
// gemm2 (fp16x1): A, B  (2 x 6144)
#define BUF2_BYTES 12288
#define OFF2_B 6144

__device__ __forceinline__ uint4 f32x8_to_h8(float4 a, float4 b) {
    uint4 r;
    __half2* p = (__half2*)&r;
    p[0] = __floats2half2_rn(a.x, a.y);
    p[1] = __floats2half2_rn(a.z, a.w);
    p[2] = __floats2half2_rn(b.x, b.y);
    p[3] = __floats2half2_rn(b.z, b.w);
    return r;
}

__device__ __forceinline__ void ldsm_x4(unsigned int addr, unsigned int* r) {
    asm volatile("ldmatrix.sync.aligned.m8n8.x4.shared.b16 {%0,%1,%2,%3}, [%4];"
                 : "=r"(r[0]), "=r"(r[1]), "=r"(r[2]), "=r"(r[3]) : "r"(addr));
}
__device__ __forceinline__ void ldsm_x2(unsigned int addr, unsigned int* r) {
    asm volatile("ldmatrix.sync.aligned.m8n8.x2.shared.b16 {%0,%1}, [%2];"
                 : "=r"(r[0]), "=r"(r[1]) : "r"(addr));
}
__device__ __forceinline__ void mma_f16(float* c, const unsigned int* a,
                                        const unsigned int* b) {
    asm volatile(
        "mma.sync.aligned.m16n8k16.row.col.f32.f16.f16.f32 "
        "{%0,%1,%2,%3}, {%4,%5,%6,%7}, {%8,%9}, {%0,%1,%2,%3};"
        : "+f"(c[0]), "+f"(c[1]), "+f"(c[2]), "+f"(c[3])
        : "r"(a[0]), "r"(a[1]), "r"(a[2]), "r"(a[3]), "r"(b[0]), "r"(b[1]));
}

// ---- GEMM1: A fp32->fp16 on the fly, W fp16 hi/lo, 2 MMAs/k; out=fp16(A@W) -
__global__ __launch_bounds__(256) void gemm1_kernel(
    const float* __restrict__ A,
    const unsigned short* __restrict__ Whi,
    const unsigned short* __restrict__ Wlo,
    __half* __restrict__ out, int K)
{
    __shared__ __align__(16) unsigned char smem[2 * BUF1_BYTES];
    unsigned int sbase = (unsigned int)__cvta_generic_to_shared(smem);
    int tid = threadIdx.x, lane = tid & 31, wid = tid >> 5;
    int wm = wid & 1, wn = wid >> 1;
    int m0 = blockIdx.y * 128, n0 = blockIdx.x * 128;

    float acc[4][4][4];
#pragma unroll
    for (int i = 0; i < 4; i++)
#pragma unroll
        for (int j = 0; j < 4; j++)
#pragma unroll
            for (int q = 0; q < 4; q++) acc[i][j][q] = 0.f;

    int ar = tid >> 1, ac = tid & 1;      // row 0..127, 8-col chunk 0..1
    const int niter = K / GBK;
    float4 stA0, stA1;

    // prologue: tile 0
    stA0 = *(const float4*)&A[(size_t)(m0 + ar) * K + ac * 8];
    stA1 = *(const float4*)&A[(size_t)(m0 + ar) * K + ac * 8 + 4];
    cp_async16(smem + OFF1_BHI + ar * SM_STRIDE + ac * 16, &Whi[(size_t)(n0 + ar) * K + ac * 8]);
    cp_async16(smem + OFF1_BLO + ar * SM_STRIDE + ac * 16, &Wlo[(size_t)(n0 + ar) * K + ac * 8]);
    asm volatile("cp.async.commit_group;" ::: "memory");
    *(uint4*)(smem + ar * SM_STRIDE + ac * 16) = f32x8_to_h8(stA0, stA1);
    asm volatile("cp.async.wait_group 0;" ::: "memory");
    __syncthreads();

    int aRow = wm * 64 + ((lane >> 3) & 1) * 8 + (lane & 7);
    int aKb  = (lane >> 4) * 16;
    int l4 = lane & 15;
    int bRow = wn * 32 + (l4 & 7);
    int bKb  = (l4 >> 3) * 16;

    int buf = 0;
    for (int it = 0; it < niter; it++) {
        if (it + 1 < niter) {
            stA0 = *(const float4*)&A[(size_t)(m0 + ar) * K + (it + 1) * GBK + ac * 8];
            stA1 = *(const float4*)&A[(size_t)(m0 + ar) * K + (it + 1) * GBK + ac * 8 + 4];
            unsigned char* nb = smem + (buf ^ 1) * BUF1_BYTES;
            cp_async16(nb + OFF1_BHI + ar * SM_STRIDE + ac * 16,
                       &Whi[(size_t)(n0 + ar) * K + (it + 1) * GBK + ac * 8]);
            cp_async16(nb + OFF1_BLO + ar * SM_STRIDE + ac * 16,
                       &Wlo[(size_t)(n0 + ar) * K + (it + 1) * GBK + ac * 8]);
            asm volatile("cp.async.commit_group;" ::: "memory");
        }

        unsigned int base = sbase + buf * BUF1_BYTES;
        unsigned int aF[4][4], bHi[4][2], bLo[4][2];
#pragma unroll
        for (int mt = 0; mt < 4; mt++)
            ldsm_x4(base + (aRow + mt * 16) * SM_STRIDE + aKb, aF[mt]);
#pragma unroll
        for (int nt = 0; nt < 4; nt++) {
            unsigned int rb = base + OFF1_BHI + (bRow + nt * 8) * SM_STRIDE + bKb;
            ldsm_x2(rb, bHi[nt]);
            ldsm_x2(rb + (OFF1_BLO - OFF1_BHI), bLo[nt]);
        }
#pragma unroll
        for (int mt = 0; mt < 4; mt++)
#pragma unroll
            for (int nt = 0; nt < 4; nt++) {
                mma_f16(acc[mt][nt], aF[mt], bHi[nt]);
                mma_f16(acc[mt][nt], aF[mt], bLo[nt]);
            }

        if (it + 1 < niter) {
            unsigned char* nb = smem + (buf ^ 1) * BUF1_BYTES;
            *(uint4*)(nb + ar * SM_STRIDE + ac * 16) = f32x8_to_h8(stA0, stA1);
            asm volatile("cp.async.wait_group 0;" ::: "memory");
        }
        __syncthreads();
        buf ^= 1;
    }

    int cm = lane >> 2, cn = (lane & 3) * 2;
#pragma unroll
    for (int mt = 0; mt < 4; mt++) {
        int row = m0 + wm * 64 + mt * 16 + cm;
#pragma unroll
        for (int nt = 0; nt < 4; nt++) {
            int col = n0 + wn * 32 + nt * 8 + cn;
            *(__half2*)&out[(size_t)row * F + col] =
                __floats2half2_rn(acc[mt][nt][0], acc[mt][nt][1]);
            *(__half2*)&out[(size_t)(row + 8) * F + col] =
                __floats2half2_rn(acc[mt][nt][2], acc[mt][nt][3]);
        }
    }
}

// ---- GEMM2: A fp16, W fp16, single pass; out = fp16(dis[m]*(A@W)) ----------
__global__ __launch_bounds__(256) void gemm2_kernel(
    const __half* __restrict__ A,
    const unsigned short* __restrict__ Wf,
    __half* __restrict__ out, int K)
{
    __shared__ __align__(16) unsigned char smem[2 * BUF2_BYTES];
    unsigned int sbase = (unsigned int)__cvta_generic_to_shared(smem);
    int tid = threadIdx.x, lane = tid & 31, wid = tid >> 5;
    int wm = wid & 1, wn = wid >> 1;
    int m0 = blockIdx.y * 128, n0 = blockIdx.x * 128;

    float acc[4][4][4];
#pragma unroll
    for (int i = 0; i < 4; i++)
#pragma unroll
        for (int j = 0; j < 4; j++)
#pragma unroll
            for (int q = 0; q < 4; q++) acc[i][j][q] = 0.f;

    int ar = tid >> 1, ac = tid & 1;
    const int niter = K / GBK;

    cp_async16(smem + ar * SM_STRIDE + ac * 16, &A[(size_t)(m0 + ar) * K + ac * 8]);
    cp_async16(smem + OFF2_B + ar * SM_STRIDE + ac * 16, &Wf[(size_t)(n0 + ar) * K + ac * 8]);
    asm volatile("cp.async.commit_group;" ::: "memory");

    int aRow = wm * 64 + ((lane >> 3) & 1) * 8 + (lane & 7);
    int aKb  = (lane >> 4) * 16;
    int l4 = lane & 15;
    int bRow = wn * 32 + (l4 & 7);
    int bKb  = (l4 >> 3) * 16;

    int buf = 0;
    for (int it = 0; it < niter; it++) {
        if (it + 1 < niter) {
            unsigned char* nb = smem + (buf ^ 1) * BUF2_BYTES;
            cp_async16(nb + ar * SM_STRIDE + ac * 16,
                       &A[(size_t)(m0 + ar) * K + (it + 1) * GBK + ac * 8]);
            cp_async16(nb + OFF2_B + ar * SM_STRIDE + ac * 16,
                       &Wf[(size_t)(n0 + ar) * K + (it + 1) * GBK + ac * 8]);
            asm volatile("cp.async.commit_group;" ::: "memory");
            asm volatile("cp.async.wait_group 1;" ::: "memory");
        } else {
            asm volatile("cp.async.wait_group 0;" ::: "memory");
        }
        __syncthreads();

        unsigned int base = sbase + buf * BUF2_BYTES;
        unsigned int aF[4][4], bF[4][2];
#pragma unroll
        for (int mt = 0; mt < 4; mt++)
            ldsm_x4(base + (aRow + mt * 16) * SM_STRIDE + aKb, aF[mt]);
#pragma unroll
        for (int nt = 0; nt < 4; nt++)
            ldsm_x2(base + OFF2_B + (bRow + nt * 8) * SM_STRIDE + bKb, bF[nt]);
#pragma unroll
        for (int mt = 0; mt < 4; mt++)
#pragma unroll
            for (int nt = 0; nt < 4; nt++)
                mma_f16(acc[mt][nt], aF[mt], bF[nt]);
        __syncthreads();
        buf ^= 1;
    }

    int cm = lane >> 2, cn = (lane & 3) * 2;
#pragma unroll
    for (int mt = 0; mt < 4; mt++) {
        int row = m0 + wm * 64 + mt * 16 + cm;
        float d1 = g_dis[row], d2 = g_dis[row + 8];
#pragma unroll
        for (int nt = 0; nt < 4; nt++) {
            int col = n0 + wn * 32 + nt * 8 + cn;
            *(__half2*)&out[(size_t)row * F + col] =
                __floats2half2_rn(d1 * acc[mt][nt][0], d1 * acc[mt][nt][1]);
            *(__half2*)&out[(size_t)(row + 8) * F + col] =
                __floats2half2_rn(d2 * acc[mt][nt][2], d2 * acc[mt][nt][3]);
        }
    }
}

// ---------------- Aggregation ------------------------------------------------
__device__ __forceinline__ void acc8w(float* a, uint4 v, float w) {
    float2 f0 = __half22float2(*(__half2*)&v.x);
    float2 f1 = __half22float2(*(__half2*)&v.y);
    float2 f2 = __half22float2(*(__half2*)&v.z);
    float2 f3 = __half22float2(*(__half2*)&v.w);
    a[0] = fmaf(w, f0.x, a[0]); a[1] = fmaf(w, f0.y, a[1]);
    a[2] = fmaf(w, f1.x, a[2]); a[3] = fmaf(w, f1.y, a[3]);
    a[4] = fmaf(w, f2.x, a[4]); a[5] = fmaf(w, f2.y, a[5]);
    a[6] = fmaf(w, f3.x, a[6]); a[7] = fmaf(w, f3.y, a[7]);
}
__device__ __forceinline__ void acc8(float* a, uint4 v) {
    float2 f0 = __half22float2(*(__half2*)&v.x);
    float2 f1 = __half22float2(*(__half2*)&v.y);
    float2 f2 = __half22float2(*(__half2*)&v.z);
    float2 f3 = __half22float2(*(__half2*)&v.w);
    a[0] += f0.x; a[1] += f0.y; a[2] += f1.x; a[3] += f1.y;
    a[4] += f2.x; a[5] += f2.y; a[6] += f3.x; a[7] += f3.y;
}

// agg1: weighted gather (dis[src] folded here),
// out16[dst] = fp16(relu(dis[dst]*(sum dis[s]*hps[s] + dis[dst]*hps[dst]) + b))
__global__ __launch_bounds__(256) void agg1_kernel(
    const __half* __restrict__ hp, const float* __restrict__ bias,
    __half* __restrict__ out)
{
    int dst = (blockIdx.x * blockDim.x + threadIdx.x) >> 5;
    if (dst >= N_TOTAL) return;
    int lane = threadIdx.x & 31;
    const uint4* hp4 = (const uint4*)hp;
    float dd = g_dis[dst];

    float a[8] = {0.f, 0.f, 0.f, 0.f, 0.f, 0.f, 0.f, 0.f};
    acc8w(a, hp4[(size_t)dst * 32 + lane], dd);   // self loop

    int e = g_rowptr[dst], end = g_rowptr[dst + 1];
    for (; e + 4 <= end; e += 4) {
        int s0 = g_col[e], s1 = g_col[e + 1], s2 = g_col[e + 2], s3 = g_col[e + 3];
        float w0 = g_dis[s0], w1 = g_dis[s1], w2 = g_dis[s2], w3 = g_dis[s3];
        uint4 v0 = hp4[(size_t)s0 * 32 + lane];
        uint4 v1 = hp4[(size_t)s1 * 32 + lane];
        uint4 v2 = hp4[(size_t)s2 * 32 + lane];
        uint4 v3 = hp4[(size_t)s3 * 32 + lane];
        acc8w(a, v0, w0); acc8w(a, v1, w1); acc8w(a, v2, w2); acc8w(a, v3, w3);
    }
    for (; e < end; e++) {
        int s0 = g_col[e];
        acc8w(a, hp4[(size_t)s0 * 32 + lane], g_dis[s0]);
    }

    const float4* b4 = (const float4*)bias;
    float4 b0 = b4[lane * 2], b1 = b4[lane * 2 + 1];
    float r[8];
    r[0] = fmaxf(fmaf(dd, a[0], b0.x), 0.f); r[1] = fmaxf(fmaf(dd, a[1], b0.y), 0.f);
    r[2] = fmaxf(fmaf(dd, a[2], b0.z), 0.f); r[3] = fmaxf(fmaf(dd, a[3], b0.w), 0.f);
    r[4] = fmaxf(fmaf(dd, a[4], b1.x), 0.f); r[5] = fmaxf(fmaf(dd, a[5], b1.y), 0.f);
    r[6] = fmaxf(fmaf(dd, a[6], b1.z), 0.f); r[7] = fmaxf(fmaf(dd, a[7], b1.w), 0.f);
    uint4 o;
    __half2* oh = (__half2*)&o;
    oh[0] = __floats2half2_rn(r[0], r[1]);
    oh[1] = __floats2half2_rn(r[2], r[3]);
    oh[2] = __floats2half2_rn(r[4], r[5]);
    oh[3] = __floats2half2_rn(r[6], r[7]);
    ((uint4*)out)[(size_t)dst * 32 + lane] = o;
}

// agg2: plain gather (dis[src] prefolded by gemm2 epilogue), fp16 out
__global__ __launch_bounds__(256) void agg2_kernel(
    const __half* __restrict__ hp, const float* __restrict__ bias,
    __half* __restrict__ out)
{
    int dst = (blockIdx.x * blockDim.x + threadIdx.x) >> 5;
    if (dst >= N_TOTAL) return;
    int lane = threadIdx.x & 31;
    const uint4* hp4 = (const uint4*)hp;

    float a[8];
    {
        uint4 v = hp4[(size_t)dst * 32 + lane];
        float2 f0 = __half22float2(*(__half2*)&v.x);
        float2 f1 = __half22float2(*(__half2*)&v.y);
        float2 f2 = __half22float2(*(__half2*)&v.z);
        float2 f3 = __half22float2(*(__half2*)&v.w);
        a[0] = f0.x; a[1] = f0.y; a[2] = f1.x; a[3] = f1.y;
        a[4] = f2.x; a[5] = f2.y; a[6] = f3.x; a[7] = f3.y;
    }
    int e = g_rowptr[dst], end = g_rowptr[dst + 1];
    for (; e + 4 <= end; e += 4) {
        int s0 = g_col[e], s1 = g_col[e + 1], s2 = g_col[e + 2], s3 = g_col[e + 3];
        uint4 v0 = hp4[(size_t)s0 * 32 + lane];
        uint4 v1 = hp4[(size_t)s1 * 32 + lane];
        uint4 v2 = hp4[(size_t)s2 * 32 + lane];
        uint4 v3 = hp4[(size_t)s3 * 32 + lane];
        acc8(a, v0); acc8(a, v1); acc8(a, v2); acc8(a, v3);
    }
    for (; e < end; e++) acc8(a, hp4[(size_t)g_col[e] * 32 + lane]);

    float dd = g_dis[dst];
    const float4* b4 = (const float4*)bias;
    float4 b0 = b4[lane * 2], b1 = b4[lane * 2 + 1];
    uint4 o;
    __half2* oh = (__half2*)&o;
    oh[0] = __floats2half2_rn(fmaf(dd, a[0], b0.x), fmaf(dd, a[1], b0.y));
    oh[1] = __floats2half2_rn(fmaf(dd, a[2], b0.z), fmaf(dd, a[3], b0.w));
    oh[2] = __floats2half2_rn(fmaf(dd, a[4], b1.x), fmaf(dd, a[5], b1.y));
    oh[3] = __floats2half2_rn(fmaf(dd, a[6], b1.z), fmaf(dd, a[7], b1.w));
    ((uint4*)out)[(size_t)dst * 32 + lane] = o;
}

// ---------------- readout (meanmax, fp16 in) + final linear ------------------
__global__ __launch_bounds__(256) void readout_kernel(
    const __half* __restrict__ h, const float* __restrict__ Wm,
    const float* __restrict__ bm, float* __restrict__ out)
{
    int g = blockIdx.x;
    int t = threadIdx.x;
    const __half* base = h + (size_t)g * NODES_PER_G * F;
    float s = 0.f, mx = -INFINITY;
    for (int i = 0; i < NODES_PER_G; i++) {
        float v = __half2float(base[(size_t)i * F + t]);
        s += v;
        mx = fmaxf(mx, v);
    }
    __shared__ float gf[2 * F];
    gf[t]     = s * (1.0f / NODES_PER_G);
    gf[F + t] = mx;
    __syncthreads();

    float p0 = gf[t] * Wm[t * 2 + 0] + gf[F + t] * Wm[(F + t) * 2 + 0];
    float p1 = gf[t] * Wm[t * 2 + 1] + gf[F + t] * Wm[(F + t) * 2 + 1];
    __shared__ float r0[256], r1[256];
    r0[t] = p0; r1[t] = p1;
    __syncthreads();
    for (int off = 128; off > 0; off >>= 1) {
        if (t < off) { r0[t] += r0[t + off]; r1[t] += r1[t + off]; }
        __syncthreads();
    }
    if (t == 0) {
        out[g * 2 + 0] = r0[0] + bm[0];
        out[g * 2 + 1] = r1[0] + bm[1];
    }
}

// ---------------- launcher --------------------------------------------------
// ONE side stream (harness-proven resource pattern).
//   s1:   CSR build (count/scan/fill) after detect
//   main: memsets, detect, wsplits, gemm1 (overlaps CSR), [join]
//         agg1 -> gemm2 -> agg2 -> readout (serial: agg owns the L2)
extern "C" void kernel_launch(void* const* d_in, const int* in_sizes, int n_in,
                              void* d_out, int out_size)
{
    int base = (in_sizes[3] == 1) ? 4 : 3;
    const float* x  = (const float*)d_in[0];
    const void*  ei = d_in[1];
    const float* W1 = (const float*)d_in[base + 0];
    const float* b1 = (const float*)d_in[base + 1];
    const float* W2 = (const float*)d_in[base + 2];
    const float* b2 = (const float*)d_in[base + 3];
    const float* Wm = (const float*)d_in[base + 4];
    const float* bm = (const float*)d_in[base + 5];
    float* out = (float*)d_out;

    __half *hps, *p16;
    unsigned short *w1hi, *w1lo, *w2f;
    int *degp, *curp;
    cudaGetSymbolAddress((void**)&hps,  g_hps);
    cudaGetSymbolAddress((void**)&p16,  g_p16);
    cudaGetSymbolAddress((void**)&w1hi, g_w1hi);
    cudaGetSymbolAddress((void**)&w1lo, g_w1lo);
    cudaGetSymbolAddress((void**)&w2f,  g_w2f);
    cudaGetSymbolAddress((void**)&degp, g_deg);
    cudaGetSymbolAddress((void**)&curp, g_cursor);

    cudaStream_t s1;
    cudaStreamCreateWithFlags(&s1, cudaStreamNonBlocking);
    cudaEvent_t evFork, evJoin;
    cudaEventCreateWithFlags(&evFork, cudaEventDisableTiming);
    cudaEventCreateWithFlags(&evJoin, cudaEventDisableTiming);

    const int TB = 256;
    dim3 gg(2, N_TOTAL / 128);

    // --- main prefix
    cudaMemsetAsync(degp, 0, N_TOTAL * sizeof(int), 0);
    cudaMemsetAsync(curp, 0, N_TOTAL * sizeof(int), 0);
    detect_kernel<<<1, 1024>>>((const unsigned int*)ei);
    cudaEventRecord(evFork, 0);

    // --- side stream: full CSR build
    cudaStreamWaitEvent(s1, evFork, 0);
    count_kernel<<<(E_TOTAL / 2 + TB - 1) / TB, TB, 0, s1>>>(ei);
    scan1_kernel<<<400, 256, 0, s1>>>();
    scan2_kernel<<<1, 512, 0, s1>>>();
    scan3_kernel<<<400, 256, 0, s1>>>();
    fill_kernel<<<(E_TOTAL / 2 + TB - 1) / TB, TB, 0, s1>>>(ei);
    cudaEventRecord(evJoin, s1);

    // --- main: weight prep + gemm1 overlap the CSR build
    wsplit_f16_kernel<<<(400 * 256 + TB - 1) / TB, TB>>>(W1, 400, w1hi, w1lo);
    wconv_f16_kernel<<<(256 * 256 + TB - 1) / TB, TB>>>(W2, 256, w2f);
    gemm1_kernel<<<gg, 256>>>(x, w1hi, w1lo, hps, 400);   // hps = fp16(x@W1)
    cudaStreamWaitEvent(0, evJoin, 0);                    // need dis + CSR
    // serial back half — agg kernels own the L2
    agg1_kernel<<<N_TOTAL / 8, 256>>>(hps, b1, p16);      // weighted gather + relu
    gemm2_kernel<<<gg, 256>>>(p16, w2f, hps, 256);        // hps = fp16(dis*(p16@W2))
    agg2_kernel<<<N_TOTAL / 8, 256>>>(hps, b2, p16);      // plain gather -> fp16 (p16 free)
    readout_kernel<<<NUM_G, 256>>>(p16, Wm, bm, out);
}

// round 16
// speedup vs baseline: 1.2240x; 1.0330x over previous
#include <cuda_runtime.h>
#include <cuda_fp16.h>
#include <math.h>

#define N_TOTAL 102400
#define E_TOTAL 4096000
#define F 256
#define NODES_PER_G 400
#define NUM_G 256

// ---------------- scratch (device globals; no allocation allowed) -----------
__device__ int   g_deg[N_TOTAL];
__device__ int   g_rank[E_TOTAL];              // per-edge slot rank (from count)
__device__ int   g_rowptr[N_TOTAL + 1];
__device__ int   g_boff[401];
__device__ int   g_col[E_TOTAL];
__device__ float g_dis[N_TOTAL];
__device__ __half g_hps[(size_t)N_TOTAL * F];  // gemm out / agg in (both layers)
__device__ __half g_p16[(size_t)N_TOTAL * F];  // agg1 out / gemm2 in
__device__ float  g_buf[(size_t)N_TOTAL * F];  // agg2 out (fp32) / readout in
__device__ int   g_is64;
// W1 fp16 [256][400]; W2 fp16 [256][256]  (both transposed, single precision pass)
__device__ unsigned short g_w1f[256 * 400];
__device__ unsigned short g_w2f[256 * 256];

__device__ __forceinline__ void cp_async16(void* smem_dst, const void* gmem_src) {
    unsigned long long sa = __cvta_generic_to_shared(smem_dst);
    asm volatile("cp.async.cg.shared.global [%0], [%1], 16;"
                 :: "l"(sa), "l"(gmem_src) : "memory");
}

// ---------------- setup kernels --------------------------------------------
__global__ void detect_kernel(const unsigned int* __restrict__ w) {
    __shared__ int any;
    if (threadIdx.x == 0) any = 0;
    __syncthreads();
    int idx = 1 + 2 * (int)threadIdx.x;
    if (w[idx] != 0u) atomicOr(&any, 1);
    __syncthreads();
    if (threadIdx.x == 0) g_is64 = (any ? 0 : 1);
}

// count degrees AND record each edge's slot rank (atomicAdd return value)
__global__ void count_kernel(const void* __restrict__ ei) {
    int t = blockIdx.x * blockDim.x + threadIdx.x;
    if (t * 2 >= E_TOTAL) return;
    int d0, d1;
    if (g_is64) {
        longlong2 d = ((const longlong2*)((const long long*)ei + E_TOTAL))[t];
        d0 = (int)d.x; d1 = (int)d.y;
    } else {
        int2 d = ((const int2*)((const int*)ei + E_TOTAL))[t];
        d0 = d.x; d1 = d.y;
    }
    g_rank[2 * t]     = atomicAdd(&g_deg[d0], 1);
    g_rank[2 * t + 1] = atomicAdd(&g_deg[d1], 1);
}

__global__ void scan1_kernel() {
    __shared__ int s[256];
    int b = blockIdx.x, tid = threadIdx.x;
    int i = b * 256 + tid;
    int d = g_deg[i];
    g_dis[i] = rsqrtf((float)(d + 1));
    s[tid] = d;
    __syncthreads();
#pragma unroll
    for (int off = 1; off < 256; off <<= 1) {
        int t = 0;
        if (tid >= off) t = s[tid - off];
        __syncthreads();
        s[tid] += t;
        __syncthreads();
    }
    g_rowptr[i] = s[tid] - d;
    if (tid == 255) g_boff[b] = s[255];
}

__global__ void scan2_kernel() {
    __shared__ int s[512];
    int tid = threadIdx.x;
    int v = (tid < 400) ? g_boff[tid] : 0;
    s[tid] = v;
    __syncthreads();
#pragma unroll
    for (int off = 1; off < 512; off <<= 1) {
        int t = 0;
        if (tid >= off) t = s[tid - off];
        __syncthreads();
        s[tid] += t;
        __syncthreads();
    }
    if (tid <= 400) g_boff[tid] = s[tid] - v;
}

__global__ void scan3_kernel() {
    int b = blockIdx.x, tid = threadIdx.x;
    int i = b * 256 + tid;
    g_rowptr[i] += g_boff[b];
    if (i == N_TOTAL - 1) g_rowptr[N_TOTAL] = g_boff[400];
}

// atomic-free scatter using precomputed ranks
__global__ void fill_kernel(const void* __restrict__ ei) {
    int t = blockIdx.x * blockDim.x + threadIdx.x;
    if (t * 2 >= E_TOTAL) return;
    int s0, s1, d0, d1;
    if (g_is64) {
        longlong2 s = ((const longlong2*)ei)[t];
        longlong2 d = ((const longlong2*)((const long long*)ei + E_TOTAL))[t];
        s0 = (int)s.x; s1 = (int)s.y; d0 = (int)d.x; d1 = (int)d.y;
    } else {
        int2 s = ((const int2*)ei)[t];
        int2 d = ((const int2*)((const int*)ei + E_TOTAL))[t];
        s0 = s.x; s1 = s.y; d0 = d.x; d1 = d.y;
    }
    int2 r = ((const int2*)g_rank)[t];
    g_col[g_rowptr[d0] + r.x] = s0;
    g_col[g_rowptr[d1] + r.y] = s1;
}

// ---------------- weight prep: plain fp16 convert + transpose ---------------
__global__ void wconv_f16_kernel(const float* __restrict__ W, int K,
                                 unsigned short* __restrict__ hi) {
    int idx = blockIdx.x * blockDim.x + threadIdx.x;
    if (idx >= K * 256) return;
    int n = idx / K, k = idx % K;
    hi[(size_t)n * K + k] = __half_as_ushort(__float2half_rn(W[(size_t)k * 256 + n]));
}

// ---------------- shared GEMM machinery -------------------------------------
#define GBK 16
#define SM_STRIDE 48
// both gemms: A, B  (2 x 6144)
#define BUF_BYTES 12288
#define OFF_B 6144

__device__ __forceinline__ uint4 f32x8_to_h8(float4 a, float4 b) {
    uint4 r;
    __half2* p = (__half2*)&r;
    p[0] = __floats2half2_rn(a.x, a.y);
    p[1] = __floats2half2_rn(a.z, a.w);
    p[2] = __floats2half2_rn(b.x, b.y);
    p[3] = __floats2half2_rn(b.z, b.w);
    return r;
}

__device__ __forceinline__ void ldsm_x4(unsigned int addr, unsigned int* r) {
    asm volatile("ldmatrix.sync.aligned.m8n8.x4.shared.b16 {%0,%1,%2,%3}, [%4];"
                 : "=r"(r[0]), "=r"(r[1]), "=r"(r[2]), "=r"(r[3]) : "r"(addr));
}
__device__ __forceinline__ void ldsm_x2(unsigned int addr, unsigned int* r) {
    asm volatile("ldmatrix.sync.aligned.m8n8.x2.shared.b16 {%0,%1}, [%2];"
                 : "=r"(r[0]), "=r"(r[1]) : "r"(addr));
}
__device__ __forceinline__ void mma_f16(float* c, const unsigned int* a,
                                        const unsigned int* b) {
    asm volatile(
        "mma.sync.aligned.m16n8k16.row.col.f32.f16.f16.f32 "
        "{%0,%1,%2,%3}, {%4,%5,%6,%7}, {%8,%9}, {%0,%1,%2,%3};"
        : "+f"(c[0]), "+f"(c[1]), "+f"(c[2]), "+f"(c[3])
        : "r"(a[0]), "r"(a[1]), "r"(a[2]), "r"(a[3]), "r"(b[0]), "r"(b[1]));
}

// ---- GEMM1: A fp32->fp16 on the fly, W fp16, single pass; out = fp16(A@W) --
__global__ __launch_bounds__(256) void gemm1_kernel(
    const float* __restrict__ A,
    const unsigned short* __restrict__ Wf,
    __half* __restrict__ out, int K)
{
    __shared__ __align__(16) unsigned char smem[2 * BUF_BYTES];
    unsigned int sbase = (unsigned int)__cvta_generic_to_shared(smem);
    int tid = threadIdx.x, lane = tid & 31, wid = tid >> 5;
    int wm = wid & 1, wn = wid >> 1;
    int m0 = blockIdx.y * 128, n0 = blockIdx.x * 128;

    float acc[4][4][4];
#pragma unroll
    for (int i = 0; i < 4; i++)
#pragma unroll
        for (int j = 0; j < 4; j++)
#pragma unroll
            for (int q = 0; q < 4; q++) acc[i][j][q] = 0.f;

    int ar = tid >> 1, ac = tid & 1;
    const int niter = K / GBK;
    float4 stA0, stA1;

    // prologue: tile 0
    stA0 = *(const float4*)&A[(size_t)(m0 + ar) * K + ac * 8];
    stA1 = *(const float4*)&A[(size_t)(m0 + ar) * K + ac * 8 + 4];
    cp_async16(smem + OFF_B + ar * SM_STRIDE + ac * 16, &Wf[(size_t)(n0 + ar) * K + ac * 8]);
    asm volatile("cp.async.commit_group;" ::: "memory");
    *(uint4*)(smem + ar * SM_STRIDE + ac * 16) = f32x8_to_h8(stA0, stA1);
    asm volatile("cp.async.wait_group 0;" ::: "memory");
    __syncthreads();

    int aRow = wm * 64 + ((lane >> 3) & 1) * 8 + (lane & 7);
    int aKb  = (lane >> 4) * 16;
    int l4 = lane & 15;
    int bRow = wn * 32 + (l4 & 7);
    int bKb  = (l4 >> 3) * 16;

    int buf = 0;
    for (int it = 0; it < niter; it++) {
        if (it + 1 < niter) {
            stA0 = *(const float4*)&A[(size_t)(m0 + ar) * K + (it + 1) * GBK + ac * 8];
            stA1 = *(const float4*)&A[(size_t)(m0 + ar) * K + (it + 1) * GBK + ac * 8 + 4];
            unsigned char* nb = smem + (buf ^ 1) * BUF_BYTES;
            cp_async16(nb + OFF_B + ar * SM_STRIDE + ac * 16,
                       &Wf[(size_t)(n0 + ar) * K + (it + 1) * GBK + ac * 8]);
            asm volatile("cp.async.commit_group;" ::: "memory");
        }

        unsigned int base = sbase + buf * BUF_BYTES;
        unsigned int aF[4][4], bF[4][2];
#pragma unroll
        for (int mt = 0; mt < 4; mt++)
            ldsm_x4(base + (aRow + mt * 16) * SM_STRIDE + aKb, aF[mt]);
#pragma unroll
        for (int nt = 0; nt < 4; nt++)
            ldsm_x2(base + OFF_B + (bRow + nt * 8) * SM_STRIDE + bKb, bF[nt]);
#pragma unroll
        for (int mt = 0; mt < 4; mt++)
#pragma unroll
            for (int nt = 0; nt < 4; nt++)
                mma_f16(acc[mt][nt], aF[mt], bF[nt]);

        if (it + 1 < niter) {
            unsigned char* nb = smem + (buf ^ 1) * BUF_BYTES;
            *(uint4*)(nb + ar * SM_STRIDE + ac * 16) = f32x8_to_h8(stA0, stA1);
            asm volatile("cp.async.wait_group 0;" ::: "memory");
        }
        __syncthreads();
        buf ^= 1;
    }

    int cm = lane >> 2, cn = (lane & 3) * 2;
#pragma unroll
    for (int mt = 0; mt < 4; mt++) {
        int row = m0 + wm * 64 + mt * 16 + cm;
#pragma unroll
        for (int nt = 0; nt < 4; nt++) {
            int col = n0 + wn * 32 + nt * 8 + cn;
            *(__half2*)&out[(size_t)row * F + col] =
                __floats2half2_rn(acc[mt][nt][0], acc[mt][nt][1]);
            *(__half2*)&out[(size_t)(row + 8) * F + col] =
                __floats2half2_rn(acc[mt][nt][2], acc[mt][nt][3]);
        }
    }
}

// ---- GEMM2: A fp16, W fp16, single pass; out = fp16(dis[m]*(A@W)) ----------
__global__ __launch_bounds__(256) void gemm2_kernel(
    const __half* __restrict__ A,
    const unsigned short* __restrict__ Wf,
    __half* __restrict__ out, int K)
{
    __shared__ __align__(16) unsigned char smem[2 * BUF_BYTES];
    unsigned int sbase = (unsigned int)__cvta_generic_to_shared(smem);
    int tid = threadIdx.x, lane = tid & 31, wid = tid >> 5;
    int wm = wid & 1, wn = wid >> 1;
    int m0 = blockIdx.y * 128, n0 = blockIdx.x * 128;

    float acc[4][4][4];
#pragma unroll
    for (int i = 0; i < 4; i++)
#pragma unroll
        for (int j = 0; j < 4; j++)
#pragma unroll
            for (int q = 0; q < 4; q++) acc[i][j][q] = 0.f;

    int ar = tid >> 1, ac = tid & 1;
    const int niter = K / GBK;

    cp_async16(smem + ar * SM_STRIDE + ac * 16, &A[(size_t)(m0 + ar) * K + ac * 8]);
    cp_async16(smem + OFF_B + ar * SM_STRIDE + ac * 16, &Wf[(size_t)(n0 + ar) * K + ac * 8]);
    asm volatile("cp.async.commit_group;" ::: "memory");

    int aRow = wm * 64 + ((lane >> 3) & 1) * 8 + (lane & 7);
    int aKb  = (lane >> 4) * 16;
    int l4 = lane & 15;
    int bRow = wn * 32 + (l4 & 7);
    int bKb  = (l4 >> 3) * 16;

    int buf = 0;
    for (int it = 0; it < niter; it++) {
        if (it + 1 < niter) {
            unsigned char* nb = smem + (buf ^ 1) * BUF_BYTES;
            cp_async16(nb + ar * SM_STRIDE + ac * 16,
                       &A[(size_t)(m0 + ar) * K + (it + 1) * GBK + ac * 8]);
            cp_async16(nb + OFF_B + ar * SM_STRIDE + ac * 16,
                       &Wf[(size_t)(n0 + ar) * K + (it + 1) * GBK + ac * 8]);
            asm volatile("cp.async.commit_group;" ::: "memory");
            asm volatile("cp.async.wait_group 1;" ::: "memory");
        } else {
            asm volatile("cp.async.wait_group 0;" ::: "memory");
        }
        __syncthreads();

        unsigned int base = sbase + buf * BUF_BYTES;
        unsigned int aF[4][4], bF[4][2];
#pragma unroll
        for (int mt = 0; mt < 4; mt++)
            ldsm_x4(base + (aRow + mt * 16) * SM_STRIDE + aKb, aF[mt]);
#pragma unroll
        for (int nt = 0; nt < 4; nt++)
            ldsm_x2(base + OFF_B + (bRow + nt * 8) * SM_STRIDE + bKb, bF[nt]);
#pragma unroll
        for (int mt = 0; mt < 4; mt++)
#pragma unroll
            for (int nt = 0; nt < 4; nt++)
                mma_f16(acc[mt][nt], aF[mt], bF[nt]);
        __syncthreads();
        buf ^= 1;
    }

    int cm = lane >> 2, cn = (lane & 3) * 2;
#pragma unroll
    for (int mt = 0; mt < 4; mt++) {
        int row = m0 + wm * 64 + mt * 16 + cm;
        float d1 = g_dis[row], d2 = g_dis[row + 8];
#pragma unroll
        for (int nt = 0; nt < 4; nt++) {
            int col = n0 + wn * 32 + nt * 8 + cn;
            *(__half2*)&out[(size_t)row * F + col] =
                __floats2half2_rn(d1 * acc[mt][nt][0], d1 * acc[mt][nt][1]);
            *(__half2*)&out[(size_t)(row + 8) * F + col] =
                __floats2half2_rn(d2 * acc[mt][nt][2], d2 * acc[mt][nt][3]);
        }
    }
}

// ---------------- Aggregation ------------------------------------------------
__device__ __forceinline__ void acc8w(float* a, uint4 v, float w) {
    float2 f0 = __half22float2(*(__half2*)&v.x);
    float2 f1 = __half22float2(*(__half2*)&v.y);
    float2 f2 = __half22float2(*(__half2*)&v.z);
    float2 f3 = __half22float2(*(__half2*)&v.w);
    a[0] = fmaf(w, f0.x, a[0]); a[1] = fmaf(w, f0.y, a[1]);
    a[2] = fmaf(w, f1.x, a[2]); a[3] = fmaf(w, f1.y, a[3]);
    a[4] = fmaf(w, f2.x, a[4]); a[5] = fmaf(w, f2.y, a[5]);
    a[6] = fmaf(w, f3.x, a[6]); a[7] = fmaf(w, f3.y, a[7]);
}
__device__ __forceinline__ void acc8(float* a, uint4 v) {
    float2 f0 = __half22float2(*(__half2*)&v.x);
    float2 f1 = __half22float2(*(__half2*)&v.y);
    float2 f2 = __half22float2(*(__half2*)&v.z);
    float2 f3 = __half22float2(*(__half2*)&v.w);
    a[0] += f0.x; a[1] += f0.y; a[2] += f1.x; a[3] += f1.y;
    a[4] += f2.x; a[5] += f2.y; a[6] += f3.x; a[7] += f3.y;
}

// agg1: weighted gather (dis[src] folded),
// out16 = fp16(relu(dis[dst]*(sum dis[s]*hps[s] + dis[dst]*hps[dst]) + b))
__global__ __launch_bounds__(256) void agg1_kernel(
    const __half* __restrict__ hp, const float* __restrict__ bias,
    __half* __restrict__ out)
{
    int dst = (blockIdx.x * blockDim.x + threadIdx.x) >> 5;
    if (dst >= N_TOTAL) return;
    int lane = threadIdx.x & 31;
    const uint4* hp4 = (const uint4*)hp;
    float dd = g_dis[dst];

    float a[8] = {0.f, 0.f, 0.f, 0.f, 0.f, 0.f, 0.f, 0.f};
    acc8w(a, hp4[(size_t)dst * 32 + lane], dd);   // self loop

    int e = g_rowptr[dst], end = g_rowptr[dst + 1];
    for (; e + 4 <= end; e += 4) {
        int s0 = g_col[e], s1 = g_col[e + 1], s2 = g_col[e + 2], s3 = g_col[e + 3];
        float w0 = g_dis[s0], w1 = g_dis[s1], w2 = g_dis[s2], w3 = g_dis[s3];
        uint4 v0 = hp4[(size_t)s0 * 32 + lane];
        uint4 v1 = hp4[(size_t)s1 * 32 + lane];
        uint4 v2 = hp4[(size_t)s2 * 32 + lane];
        uint4 v3 = hp4[(size_t)s3 * 32 + lane];
        acc8w(a, v0, w0); acc8w(a, v1, w1); acc8w(a, v2, w2); acc8w(a, v3, w3);
    }
    for (; e < end; e++) {
        int s0 = g_col[e];
        acc8w(a, hp4[(size_t)s0 * 32 + lane], g_dis[s0]);
    }

    const float4* b4 = (const float4*)bias;
    float4 b0 = b4[lane * 2], b1 = b4[lane * 2 + 1];
    float r[8];
    r[0] = fmaxf(fmaf(dd, a[0], b0.x), 0.f); r[1] = fmaxf(fmaf(dd, a[1], b0.y), 0.f);
    r[2] = fmaxf(fmaf(dd, a[2], b0.z), 0.f); r[3] = fmaxf(fmaf(dd, a[3], b0.w), 0.f);
    r[4] = fmaxf(fmaf(dd, a[4], b1.x), 0.f); r[5] = fmaxf(fmaf(dd, a[5], b1.y), 0.f);
    r[6] = fmaxf(fmaf(dd, a[6], b1.z), 0.f); r[7] = fmaxf(fmaf(dd, a[7], b1.w), 0.f);
    uint4 o;
    __half2* oh = (__half2*)&o;
    oh[0] = __floats2half2_rn(r[0], r[1]);
    oh[1] = __floats2half2_rn(r[2], r[3]);
    oh[2] = __floats2half2_rn(r[4], r[5]);
    oh[3] = __floats2half2_rn(r[6], r[7]);
    ((uint4*)out)[(size_t)dst * 32 + lane] = o;
}

// agg2: plain gather (dis[src] prefolded by gemm2 epilogue), fp32 out
__global__ __launch_bounds__(256) void agg2_kernel(
    const __half* __restrict__ hp, const float* __restrict__ bias,
    float* __restrict__ out)
{
    int dst = (blockIdx.x * blockDim.x + threadIdx.x) >> 5;
    if (dst >= N_TOTAL) return;
    int lane = threadIdx.x & 31;
    const uint4* hp4 = (const uint4*)hp;

    float a[8];
    {
        uint4 v = hp4[(size_t)dst * 32 + lane];
        float2 f0 = __half22float2(*(__half2*)&v.x);
        float2 f1 = __half22float2(*(__half2*)&v.y);
        float2 f2 = __half22float2(*(__half2*)&v.z);
        float2 f3 = __half22float2(*(__half2*)&v.w);
        a[0] = f0.x; a[1] = f0.y; a[2] = f1.x; a[3] = f1.y;
        a[4] = f2.x; a[5] = f2.y; a[6] = f3.x; a[7] = f3.y;
    }
    int e = g_rowptr[dst], end = g_rowptr[dst + 1];
    for (; e + 4 <= end; e += 4) {
        int s0 = g_col[e], s1 = g_col[e + 1], s2 = g_col[e + 2], s3 = g_col[e + 3];
        uint4 v0 = hp4[(size_t)s0 * 32 + lane];
        uint4 v1 = hp4[(size_t)s1 * 32 + lane];
        uint4 v2 = hp4[(size_t)s2 * 32 + lane];
        uint4 v3 = hp4[(size_t)s3 * 32 + lane];
        acc8(a, v0); acc8(a, v1); acc8(a, v2); acc8(a, v3);
    }
    for (; e < end; e++) acc8(a, hp4[(size_t)g_col[e] * 32 + lane]);

    float dd = g_dis[dst];
    const float4* b4 = (const float4*)bias;
    float4 b0 = b4[lane * 2], b1 = b4[lane * 2 + 1];
    float4* o4 = (float4*)&out[(size_t)dst * F + lane * 8];
    o4[0] = make_float4(fmaf(dd, a[0], b0.x), fmaf(dd, a[1], b0.y),
                        fmaf(dd, a[2], b0.z), fmaf(dd, a[3], b0.w));
    o4[1] = make_float4(fmaf(dd, a[4], b1.x), fmaf(dd, a[5], b1.y),
                        fmaf(dd, a[6], b1.z), fmaf(dd, a[7], b1.w));
}

// ---------------- readout (meanmax) + final linear --------------------------
__global__ __launch_bounds__(256) void readout_kernel(
    const float* __restrict__ h, const float* __restrict__ Wm,
    const float* __restrict__ bm, float* __restrict__ out)
{
    int g = blockIdx.x;
    int t = threadIdx.x;
    const float* base = h + (size_t)g * NODES_PER_G * F;
    float s = 0.f, mx = -INFINITY;
    for (int i = 0; i < NODES_PER_G; i++) {
        float v = base[(size_t)i * F + t];
        s += v;
        mx = fmaxf(mx, v);
    }
    __shared__ float gf[2 * F];
    gf[t]     = s * (1.0f / NODES_PER_G);
    gf[F + t] = mx;
    __syncthreads();

    float p0 = gf[t] * Wm[t * 2 + 0] + gf[F + t] * Wm[(F + t) * 2 + 0];
    float p1 = gf[t] * Wm[t * 2 + 1] + gf[F + t] * Wm[(F + t) * 2 + 1];
    __shared__ float r0[256], r1[256];
    r0[t] = p0; r1[t] = p1;
    __syncthreads();
    for (int off = 128; off > 0; off >>= 1) {
        if (t < off) { r0[t] += r0[t + off]; r1[t] += r1[t + off]; }
        __syncthreads();
    }
    if (t == 0) {
        out[g * 2 + 0] = r0[0] + bm[0];
        out[g * 2 + 1] = r1[0] + bm[1];
    }
}

// ---------------- launcher --------------------------------------------------
// ONE side stream (harness-proven resource pattern).
//   s1:   CSR build (count[+ranks] / scan / rank-fill) after detect
//   main: memset, detect, wconvs, gemm1 (overlaps CSR), [join]
//         agg1 -> gemm2 -> agg2 -> readout (serial: agg owns the L2)
extern "C" void kernel_launch(void* const* d_in, const int* in_sizes, int n_in,
                              void* d_out, int out_size)
{
    int base = (in_sizes[3] == 1) ? 4 : 3;
    const float* x  = (const float*)d_in[0];
    const void*  ei = d_in[1];
    const float* W1 = (const float*)d_in[base + 0];
    const float* b1 = (const float*)d_in[base + 1];
    const float* W2 = (const float*)d_in[base + 2];
    const float* b2 = (const float*)d_in[base + 3];
    const float* Wm = (const float*)d_in[base + 4];
    const float* bm = (const float*)d_in[base + 5];
    float* out = (float*)d_out;

    __half *hps, *p16; float* buf;
    unsigned short *w1f, *w2f;
    int *degp;
    cudaGetSymbolAddress((void**)&hps,  g_hps);
    cudaGetSymbolAddress((void**)&p16,  g_p16);
    cudaGetSymbolAddress((void**)&buf,  g_buf);
    cudaGetSymbolAddress((void**)&w1f,  g_w1f);
    cudaGetSymbolAddress((void**)&w2f,  g_w2f);
    cudaGetSymbolAddress((void**)&degp, g_deg);

    cudaStream_t s1;
    cudaStreamCreateWithFlags(&s1, cudaStreamNonBlocking);
    cudaEvent_t evFork, evJoin;
    cudaEventCreateWithFlags(&evFork, cudaEventDisableTiming);
    cudaEventCreateWithFlags(&evJoin, cudaEventDisableTiming);

    const int TB = 256;
    dim3 gg(2, N_TOTAL / 128);

    // --- main prefix
    cudaMemsetAsync(degp, 0, N_TOTAL * sizeof(int), 0);
    detect_kernel<<<1, 1024>>>((const unsigned int*)ei);
    cudaEventRecord(evFork, 0);

    // --- side stream: CSR build (count records ranks; fill is atomic-free)
    cudaStreamWaitEvent(s1, evFork, 0);
    count_kernel<<<(E_TOTAL / 2 + TB - 1) / TB, TB, 0, s1>>>(ei);
    scan1_kernel<<<400, 256, 0, s1>>>();
    scan2_kernel<<<1, 512, 0, s1>>>();
    scan3_kernel<<<400, 256, 0, s1>>>();
    fill_kernel<<<(E_TOTAL / 2 + TB - 1) / TB, TB, 0, s1>>>(ei);
    cudaEventRecord(evJoin, s1);

    // --- main: weight prep + gemm1 overlap the CSR build
    wconv_f16_kernel<<<(400 * 256 + TB - 1) / TB, TB>>>(W1, 400, w1f);
    wconv_f16_kernel<<<(256 * 256 + TB - 1) / TB, TB>>>(W2, 256, w2f);
    gemm1_kernel<<<gg, 256>>>(x, w1f, hps, 400);          // hps = fp16(x@W1)
    cudaStreamWaitEvent(0, evJoin, 0);                    // need dis + CSR
    // serial back half — agg kernels own the L2
    agg1_kernel<<<N_TOTAL / 8, 256>>>(hps, b1, p16);      // weighted gather + relu
    gemm2_kernel<<<gg, 256>>>(p16, w2f, hps, 256);        // hps = fp16(dis*(p16@W2))
    agg2_kernel<<<N_TOTAL / 8, 256>>>(hps, b2, buf);      // plain gather, fp32
    readout_kernel<<<NUM_G, 256>>>(buf, Wm, bm, out);
}